// round 8
// baseline (speedup 1.0000x reference)
#include <cuda_runtime.h>
#include <cuda_bf16.h>
#include <cstdint>
#include <math.h>

#define D_MODEL  1024
#define N_HEADS  16
#define HEAD_DIM 64
#define BATCH    4
#define SEQ      2048
#define M_ROWS   (BATCH * SEQ)   // 8192
#define DD       (D_MODEL * D_MODEL)

// ---------------------------------------------------------------------------
// Static scratch (no cudaMalloc allowed). All attention tensors split-bf16.
// ---------------------------------------------------------------------------
__device__ __nv_bfloat16 g_QH[M_ROWS * D_MODEL];
__device__ __nv_bfloat16 g_QL[M_ROWS * D_MODEL];
__device__ __nv_bfloat16 g_KH[M_ROWS * D_MODEL];
__device__ __nv_bfloat16 g_KL[M_ROWS * D_MODEL];
__device__ __nv_bfloat16 g_VH[M_ROWS * D_MODEL];
__device__ __nv_bfloat16 g_VL[M_ROWS * D_MODEL];
__device__ __nv_bfloat16 g_XH[M_ROWS * D_MODEL];   // x, then attn-out (hi)
__device__ __nv_bfloat16 g_XL[M_ROWS * D_MODEL];   // x, then attn-out (lo)
__device__ __nv_bfloat16 g_WH[4 * DD];             // wq,wk,wv,wo hi
__device__ __nv_bfloat16 g_WL[4 * DD];             // wq,wk,wv,wo lo

// ---------------------------------------------------------------------------
// Helpers (compute_103-safe)
// ---------------------------------------------------------------------------
__device__ __forceinline__ uint32_t smem_u32(const void* p) {
    uint32_t a;
    asm("{ .reg .u64 t; cvta.to.shared.u64 t, %1; cvt.u32.u64 %0, t; }"
        : "=r"(a) : "l"(p));
    return a;
}
__device__ __forceinline__ void cp_async16(uint32_t dst, const void* src) {
    asm volatile("cp.async.cg.shared.global [%0], [%1], 16;\n"
                 :: "r"(dst), "l"(src) : "memory");
}
__device__ __forceinline__ void cp_commit() {
    asm volatile("cp.async.commit_group;\n" ::: "memory");
}
template <int N>
__device__ __forceinline__ void cp_wait() {
    asm volatile("cp.async.wait_group %0;\n" :: "n"(N) : "memory");
}
__device__ __forceinline__ void ldsm_x4(uint32_t addr, uint32_t* r) {
    asm volatile("ldmatrix.sync.aligned.m8n8.x4.shared.b16 {%0,%1,%2,%3}, [%4];\n"
                 : "=r"(r[0]), "=r"(r[1]), "=r"(r[2]), "=r"(r[3]) : "r"(addr));
}
__device__ __forceinline__ void ldsm_x4t(uint32_t addr, uint32_t* r) {
    asm volatile("ldmatrix.sync.aligned.m8n8.x4.trans.shared.b16 {%0,%1,%2,%3}, [%4];\n"
                 : "=r"(r[0]), "=r"(r[1]), "=r"(r[2]), "=r"(r[3]) : "r"(addr));
}
__device__ __forceinline__ void mma16816(float* c, const uint32_t* a,
                                         uint32_t b0, uint32_t b1) {
    asm volatile(
        "mma.sync.aligned.m16n8k16.row.col.f32.bf16.bf16.f32 "
        "{%0,%1,%2,%3}, {%4,%5,%6,%7}, {%8,%9}, {%0,%1,%2,%3};\n"
        : "+f"(c[0]), "+f"(c[1]), "+f"(c[2]), "+f"(c[3])
        : "r"(a[0]), "r"(a[1]), "r"(a[2]), "r"(a[3]), "r"(b0), "r"(b1));
}
__device__ __forceinline__ void packsplit(float x, float y,
                                          uint32_t& hi, uint32_t& lo) {
    __nv_bfloat162 H = __floats2bfloat162_rn(x, y);
    float2 Hf = __bfloat1622float2(H);
    __nv_bfloat162 L = __floats2bfloat162_rn(x - Hf.x, y - Hf.y);
    hi = *(uint32_t*)&H;
    lo = *(uint32_t*)&L;
}

// ---------------------------------------------------------------------------
// Split conversions for x and W
// ---------------------------------------------------------------------------
__device__ __forceinline__ void split4(float4 v, __nv_bfloat16* h, __nv_bfloat16* l,
                                       size_t idx4) {
    uint32_t h0, l0, h1, l1;
    packsplit(v.x, v.y, h0, l0);
    packsplit(v.z, v.w, h1, l1);
    ((uint32_t*)h)[idx4 * 2 + 0] = h0;
    ((uint32_t*)h)[idx4 * 2 + 1] = h1;
    ((uint32_t*)l)[idx4 * 2 + 0] = l0;
    ((uint32_t*)l)[idx4 * 2 + 1] = l1;
}
__global__ void conv_x(const float* __restrict__ x) {
    size_t i = (size_t)blockIdx.x * blockDim.x + threadIdx.x;
    split4(((const float4*)x)[i], g_XH, g_XL, i);
}
__global__ void conv_w(const float* __restrict__ w0, const float* __restrict__ w1,
                       const float* __restrict__ w2, const float* __restrict__ w3) {
    const float* w = (blockIdx.z == 0) ? w0 : (blockIdx.z == 1) ? w1
                   : (blockIdx.z == 2) ? w2 : w3;
    size_t i = (size_t)blockIdx.x * blockDim.x + threadIdx.x;
    split4(((const float4*)w)[i], g_WH + (size_t)blockIdx.z * DD,
           g_WL + (size_t)blockIdx.z * DD, i);
}

// ---------------------------------------------------------------------------
// Fused split-bf16 GEMM on mma.sync: per k-tile load Ah|Al|Bh|Bl once, run
// all 3 terms (AhBh + AhBl + AlBh). BK=32, 64-byte rows, swizzle c^((r>>1)&3).
// 3-stage cp.async pipeline, 32KB/stage -> 96KB, 2 CTAs/SM.
// ---------------------------------------------------------------------------
#define BK2     32
#define NK2     (D_MODEL / BK2)   // 32
#define ARR_B   8192              // bytes per array (128 rows x 64B)
#define STAGE   (4 * ARR_B)       // 32768
#define SM_GEMM (3 * STAGE)       // 98304

__device__ __forceinline__ uint32_t sw64(uint32_t r, uint32_t c) {
    return r * 64 + ((c ^ ((r >> 1) & 3)) << 4);
}

__device__ __forceinline__ void gemm_core(const __nv_bfloat16* __restrict__ Bh,
                                          const __nv_bfloat16* __restrict__ Bl,
                                          float* __restrict__ Cf,
                                          __nv_bfloat16* __restrict__ Ch,
                                          __nv_bfloat16* __restrict__ Cl,
                                          float scl)
{
    extern __shared__ char smem[];
    const uint32_t sb = smem_u32(smem);
    const int tid = threadIdx.x;
    const int wid = tid >> 5, lid = tid & 31;
    const int wm  = wid >> 2, wn = wid & 3;          // 2 x 4 warp grid, 64x32 tile
    const int bm  = blockIdx.y * 128, bn = blockIdx.x * 128;

    float acc[4][4][4];
#pragma unroll
    for (int i = 0; i < 4; i++)
#pragma unroll
        for (int j = 0; j < 4; j++)
#pragma unroll
            for (int q = 0; q < 4; q++) acc[i][j][q] = 0.f;

    // fragment smem addresses (stage-relative)
    uint32_t aAddr[4], bAddr[2];
#pragma unroll
    for (int i = 0; i < 4; i++) {
        const uint32_t row = (uint32_t)(wm * 64 + i * 16 + (lid & 15));
        aAddr[i] = sw64(row, (uint32_t)(lid >> 4));          // kstep adds ^2
    }
#pragma unroll
    for (int p = 0; p < 2; p++) {
        const uint32_t row = (uint32_t)(wn * 32 + p * 16 + (lid & 7) + ((lid >> 4) & 1) * 8);
        bAddr[p] = sw64(row, (uint32_t)((lid >> 3) & 1));
    }

    auto issue = [&](int t) {
        const uint32_t st = sb + (uint32_t)(t % 3) * STAGE;
        const int k0 = t * BK2;
#pragma unroll
        for (int u = 0; u < 8; u++) {
            const int i = tid + u * 256;              // 0..2047
            const int arr = i >> 9;                   // 0 Ah 1 Al 2 Bh 3 Bl
            const int j = i & 511;
            const int r = j >> 2, c = j & 3;
            const __nv_bfloat16* base =
                (arr == 0) ? g_XH + (size_t)(bm + r) * D_MODEL
              : (arr == 1) ? g_XL + (size_t)(bm + r) * D_MODEL
              : (arr == 2) ? Bh   + (size_t)(bn + r) * D_MODEL
                           : Bl   + (size_t)(bn + r) * D_MODEL;
            cp_async16(st + (uint32_t)arr * ARR_B + sw64((uint32_t)r, (uint32_t)c),
                       base + k0 + c * 8);
        }
        cp_commit();
    };

    issue(0);
    issue(1);
    issue(2);

#pragma unroll 1
    for (int t = 0; t < NK2; t++) {
        if (t < NK2 - 2)       cp_wait<2>();
        else if (t == NK2 - 2) cp_wait<1>();
        else                   cp_wait<0>();
        __syncthreads();

        const uint32_t st = sb + (uint32_t)(t % 3) * STAGE;
#pragma unroll
        for (int s = 0; s < 2; s++) {
            const uint32_t kx = (uint32_t)(s * 2) << 4;   // chunk ^= 2s -> +32B pre-swizzle? no: chunk index xor is linear in addr since chunk bits are addr bits [4:5]
            uint32_t ah[4][4], al[4][4], bh[2][4], bl[2][4];
#pragma unroll
            for (int i = 0; i < 4; i++) {
                ldsm_x4(st + (aAddr[i] ^ kx), ah[i]);
                ldsm_x4(st + ARR_B + (aAddr[i] ^ kx), al[i]);
            }
#pragma unroll
            for (int p = 0; p < 2; p++) {
                ldsm_x4(st + 2 * ARR_B + (bAddr[p] ^ kx), bh[p]);
                ldsm_x4(st + 3 * ARR_B + (bAddr[p] ^ kx), bl[p]);
            }
#pragma unroll
            for (int i = 0; i < 4; i++)
#pragma unroll
                for (int j = 0; j < 4; j++) {
                    const uint32_t h0 = bh[j >> 1][(j & 1) * 2], h1 = bh[j >> 1][(j & 1) * 2 + 1];
                    const uint32_t l0 = bl[j >> 1][(j & 1) * 2], l1 = bl[j >> 1][(j & 1) * 2 + 1];
                    mma16816(acc[i][j], ah[i], h0, h1);
                    mma16816(acc[i][j], ah[i], l0, l1);
                    mma16816(acc[i][j], al[i], h0, h1);
                }
        }
        __syncthreads();
        if (t + 3 < NK2) issue(t + 3);
    }

    const int g  = lid >> 2;
    const int t2 = (lid & 3) * 2;
#pragma unroll
    for (int i = 0; i < 4; i++) {
        const int row = bm + wm * 64 + i * 16 + g;
#pragma unroll
        for (int j = 0; j < 4; j++) {
            const int col = bn + wn * 32 + j * 8 + t2;
            if (Cf) {
                *(float2*)&Cf[(size_t)row * D_MODEL + col] =
                    make_float2(acc[i][j][0], acc[i][j][1]);
                *(float2*)&Cf[(size_t)(row + 8) * D_MODEL + col] =
                    make_float2(acc[i][j][2], acc[i][j][3]);
            } else {
                uint32_t h, l;
                packsplit(acc[i][j][0] * scl, acc[i][j][1] * scl, h, l);
                *(uint32_t*)&Ch[(size_t)row * D_MODEL + col] = h;
                *(uint32_t*)&Cl[(size_t)row * D_MODEL + col] = l;
                packsplit(acc[i][j][2] * scl, acc[i][j][3] * scl, h, l);
                *(uint32_t*)&Ch[(size_t)(row + 8) * D_MODEL + col] = h;
                *(uint32_t*)&Cl[(size_t)(row + 8) * D_MODEL + col] = l;
            }
        }
    }
}

__global__ void __launch_bounds__(256, 2)
gemm_qkv() {
    const int z = blockIdx.z;
    __nv_bfloat16* Ch = (z == 0) ? g_QH : (z == 1) ? g_KH : g_VH;
    __nv_bfloat16* Cl = (z == 0) ? g_QL : (z == 1) ? g_KL : g_VL;
    const float scl = (z == 0) ? 0.125f : 1.0f;      // fold 1/sqrt(64) into Q
    gemm_core(g_WH + (size_t)z * DD, g_WL + (size_t)z * DD, nullptr, Ch, Cl, scl);
}
__global__ void __launch_bounds__(256, 2)
gemm_o(float* __restrict__ out) {
    gemm_core(g_WH + 3ull * DD, g_WL + 3ull * DD, out, nullptr, nullptr, 1.f);
}

// ---------------------------------------------------------------------------
// Tensor-core causal flash attention (split-bf16, fp32 softmax/accum).
// Unchanged from R7 (862us winner). 64 queries/block, Q staged into stage0.
// ---------------------------------------------------------------------------
#define AST 33024                         // stage stride bytes
#define SM_ATTN (2 * AST)                 // 66048

__global__ void __launch_bounds__(128, 3)
attn_mma(const int* __restrict__ mask)
{
    extern __shared__ char smem[];
    const uint32_t sb = smem_u32(smem);
    const int tid = threadIdx.x, wid = tid >> 5, lid = tid & 31;
    const int qt = blockIdx.x, h = blockIdx.y, b = blockIdx.z;
    const int bm = qt * 64;
    const int nt = qt + 1;                // causal: key tiles 0..qt

    {
#pragma unroll
        for (int u = 0; u < 8; u++) {
            const int i = tid + u * 128;
            const int arr = i >> 9;
            const int j = i & 511;
            const int r = j >> 3, c = j & 7;
            const __nv_bfloat16* src = (arr ? g_QL : g_QH) +
                (size_t)(b * SEQ + bm + r) * D_MODEL + h * HEAD_DIM + c * 8;
            cp_async16(sb + (uint32_t)arr * 8192 +
                       (uint32_t)r * 128 + (uint32_t)((c ^ (r & 7)) << 4), src);
        }
        cp_commit();
        cp_wait<0>();
        __syncthreads();
    }
    uint32_t aQh[4][4], aQl[4][4];
#pragma unroll
    for (int ks = 0; ks < 4; ks++) {
        const uint32_t off = (uint32_t)(wid * 16 + (lid & 15)) * 128 +
                             (uint32_t)(((2 * ks + (lid >> 4)) ^ (lid & 7)) << 4);
        ldsm_x4(sb + off, aQh[ks]);
        ldsm_x4(sb + 8192 + off, aQl[ks]);
    }
    __syncthreads();

    auto issueKV = [&](int ti) {
        const uint32_t st = sb + (uint32_t)(ti & 1) * AST;
        const int t0 = ti * 64;
#pragma unroll
        for (int u = 0; u < 16; u++) {
            const int i = tid + u * 128;
            const int arr = i >> 9;
            const int j = i & 511;
            const int r = j >> 3, c = j & 7;
            const __nv_bfloat16* base = (arr == 0) ? g_KH : (arr == 1) ? g_KL
                                      : (arr == 2) ? g_VH : g_VL;
            const __nv_bfloat16* src = base +
                (size_t)(b * SEQ + t0 + r) * D_MODEL + h * HEAD_DIM + c * 8;
            cp_async16(st + (uint32_t)arr * 8192 +
                       (uint32_t)r * 128 + (uint32_t)((c ^ (r & 7)) << 4), src);
        }
        if (tid < 16)
            cp_async16(st + 32768 + tid * 16, mask + b * SEQ + t0 + tid * 4);
        cp_commit();
    };

    issueKV(0);
    if (nt > 1) issueKV(1);

    float oreg[8][4];
#pragma unroll
    for (int j = 0; j < 8; j++)
#pragma unroll
        for (int q = 0; q < 4; q++) oreg[j][q] = 0.f;
    float mA = -1e30f, mB = -1e30f, lA = 0.f, lB = 0.f;
    const int q0 = bm + wid * 16 + (lid >> 2);

#pragma unroll 1
    for (int ti = 0; ti < nt; ti++) {
        if (ti == nt - 1) cp_wait<0>(); else cp_wait<1>();
        __syncthreads();
        const uint32_t st = sb + (uint32_t)(ti & 1) * AST;
        const int* msk_s = (const int*)(smem + (ti & 1) * AST + 32768);
        const int t0 = ti * 64;

        float sr[8][4];
#pragma unroll
        for (int j = 0; j < 8; j++)
#pragma unroll
            for (int q = 0; q < 4; q++) sr[j][q] = 0.f;
#pragma unroll
        for (int ks = 0; ks < 4; ks++) {
            uint32_t bh[4][4], bl[4][4];
#pragma unroll
            for (int nb = 0; nb < 4; nb++) {
                const uint32_t row = (uint32_t)(nb * 16 + (lid & 7) + ((lid >> 4) & 1) * 8);
                const uint32_t off = row * 128 +
                    (uint32_t)(((2 * ks + ((lid >> 3) & 1)) ^ (lid & 7)) << 4);
                ldsm_x4(st + off, bh[nb]);
                ldsm_x4(st + 8192 + off, bl[nb]);
            }
#pragma unroll
            for (int j = 0; j < 8; j++) {
                const uint32_t b0h = bh[j >> 1][(j & 1) * 2], b1h = bh[j >> 1][(j & 1) * 2 + 1];
                const uint32_t b0l = bl[j >> 1][(j & 1) * 2], b1l = bl[j >> 1][(j & 1) * 2 + 1];
                mma16816(sr[j], aQh[ks], b0h, b1h);
                mma16816(sr[j], aQh[ks], b0l, b1l);
                mma16816(sr[j], aQl[ks], b0h, b1h);
            }
        }

        const bool diag = (ti == qt);
#pragma unroll
        for (int j = 0; j < 8; j++) {
            const int c = j * 8 + (lid & 3) * 2;
            const int kg = t0 + c;
            const int mk0 = msk_s[c], mk1 = msk_s[c + 1];
            if (!mk0) { sr[j][0] = -1e30f; sr[j][2] = -1e30f; }
            if (!mk1) { sr[j][1] = -1e30f; sr[j][3] = -1e30f; }
            if (diag) {
                if (kg     > q0)     sr[j][0] = -1e30f;
                if (kg + 1 > q0)     sr[j][1] = -1e30f;
                if (kg     > q0 + 8) sr[j][2] = -1e30f;
                if (kg + 1 > q0 + 8) sr[j][3] = -1e30f;
            }
        }
        float tmA = -1e30f, tmB = -1e30f;
#pragma unroll
        for (int j = 0; j < 8; j++) {
            tmA = fmaxf(tmA, fmaxf(sr[j][0], sr[j][1]));
            tmB = fmaxf(tmB, fmaxf(sr[j][2], sr[j][3]));
        }
        tmA = fmaxf(tmA, __shfl_xor_sync(0xffffffff, tmA, 1));
        tmA = fmaxf(tmA, __shfl_xor_sync(0xffffffff, tmA, 2));
        tmB = fmaxf(tmB, __shfl_xor_sync(0xffffffff, tmB, 1));
        tmB = fmaxf(tmB, __shfl_xor_sync(0xffffffff, tmB, 2));
        const float nmA = fmaxf(mA, tmA), nmB = fmaxf(mB, tmB);
        const float corrA = __expf(mA - nmA), corrB = __expf(mB - nmB);
        mA = nmA; mB = nmB;
        float sA = 0.f, sB = 0.f;
#pragma unroll
        for (int j = 0; j < 8; j++) {
            sr[j][0] = __expf(sr[j][0] - nmA);
            sr[j][1] = __expf(sr[j][1] - nmA);
            sr[j][2] = __expf(sr[j][2] - nmB);
            sr[j][3] = __expf(sr[j][3] - nmB);
            sA += sr[j][0] + sr[j][1];
            sB += sr[j][2] + sr[j][3];
        }
        sA += __shfl_xor_sync(0xffffffff, sA, 1);
        sA += __shfl_xor_sync(0xffffffff, sA, 2);
        sB += __shfl_xor_sync(0xffffffff, sB, 1);
        sB += __shfl_xor_sync(0xffffffff, sB, 2);
        lA = lA * corrA + sA;
        lB = lB * corrB + sB;
#pragma unroll
        for (int j = 0; j < 8; j++) {
            oreg[j][0] *= corrA; oreg[j][1] *= corrA;
            oreg[j][2] *= corrB; oreg[j][3] *= corrB;
        }

#pragma unroll
        for (int ks = 0; ks < 4; ks++) {
            uint32_t aph[4], apl[4];
            packsplit(sr[2*ks][0],   sr[2*ks][1],   aph[0], apl[0]);
            packsplit(sr[2*ks][2],   sr[2*ks][3],   aph[1], apl[1]);
            packsplit(sr[2*ks+1][0], sr[2*ks+1][1], aph[2], apl[2]);
            packsplit(sr[2*ks+1][2], sr[2*ks+1][3], aph[3], apl[3]);
            uint32_t vh[4][4], vl[4][4];
#pragma unroll
            for (int nb = 0; nb < 4; nb++) {
                const uint32_t row = (uint32_t)(ks * 16 + (lid & 7) + ((lid >> 3) & 1) * 8);
                const uint32_t chk = (uint32_t)(nb * 2 + (lid >> 4));
                const uint32_t off = row * 128 + ((chk ^ (lid & 7)) << 4);
                ldsm_x4t(st + 16384 + off, vh[nb]);
                ldsm_x4t(st + 24576 + off, vl[nb]);
            }
#pragma unroll
            for (int j = 0; j < 8; j++) {
                const uint32_t b0h = vh[j >> 1][(j & 1) * 2], b1h = vh[j >> 1][(j & 1) * 2 + 1];
                const uint32_t b0l = vl[j >> 1][(j & 1) * 2], b1l = vl[j >> 1][(j & 1) * 2 + 1];
                mma16816(oreg[j], aph, b0h, b1h);
                mma16816(oreg[j], apl, b0h, b1h);
                mma16816(oreg[j], aph, b0l, b1l);
            }
        }

        __syncthreads();
        if (ti + 2 < nt) issueKV(ti + 2);
    }

    const float invA = 1.f / lA, invB = 1.f / lB;
    const size_t rA = (size_t)(b * SEQ + q0) * D_MODEL + h * HEAD_DIM;
    const size_t rB = rA + 8ull * D_MODEL;
#pragma unroll
    for (int j = 0; j < 8; j++) {
        const int col = j * 8 + (lid & 3) * 2;
        uint32_t hh, ll;
        packsplit(oreg[j][0] * invA, oreg[j][1] * invA, hh, ll);
        *(uint32_t*)&g_XH[rA + col] = hh;
        *(uint32_t*)&g_XL[rA + col] = ll;
        packsplit(oreg[j][2] * invB, oreg[j][3] * invB, hh, ll);
        *(uint32_t*)&g_XH[rB + col] = hh;
        *(uint32_t*)&g_XL[rB + col] = ll;
    }
}

// ---------------------------------------------------------------------------
// Launch. Inputs: x, attention_mask, wq, wk, wv, wo. Output fp32.
// ---------------------------------------------------------------------------
extern "C" void kernel_launch(void* const* d_in, const int* in_sizes, int n_in,
                              void* d_out, int out_size)
{
    const float* x    = (const float*)d_in[0];
    const int*   amsk = (const int*)  d_in[1];
    const float* wq   = (const float*)d_in[2];
    const float* wk   = (const float*)d_in[3];
    const float* wv   = (const float*)d_in[4];
    const float* wo   = (const float*)d_in[5];
    float*       out  = (float*)d_out;

    cudaFuncSetAttribute(gemm_qkv, cudaFuncAttributeMaxDynamicSharedMemorySize, SM_GEMM);
    cudaFuncSetAttribute(gemm_o,   cudaFuncAttributeMaxDynamicSharedMemorySize, SM_GEMM);
    cudaFuncSetAttribute(attn_mma, cudaFuncAttributeMaxDynamicSharedMemorySize, SM_ATTN);

    conv_x<<<M_ROWS * D_MODEL / 4 / 256, 256>>>(x);
    conv_w<<<dim3(DD / 4 / 256, 1, 4), 256>>>(wq, wk, wv, wo);

    dim3 gQKV(D_MODEL / 128, M_ROWS / 128, 3);   // (8, 64, 3)
    gemm_qkv<<<gQKV, 256, SM_GEMM>>>();

    dim3 gAttn(SEQ / 64, N_HEADS, BATCH);        // (32, 16, 4)
    attn_mma<<<gAttn, 128, SM_ATTN>>>(amsk);

    dim3 gOut(D_MODEL / 128, M_ROWS / 128, 1);
    gemm_o<<<gOut, 256, SM_GEMM>>>(out);
}

// round 9
// speedup vs baseline: 2.1998x; 2.1998x over previous
#include <cuda_runtime.h>
#include <cuda_fp16.h>
#include <cstdint>
#include <math.h>

#define D_MODEL  1024
#define N_HEADS  16
#define HEAD_DIM 64
#define BATCH    4
#define SEQ      2048
#define M_ROWS   (BATCH * SEQ)   // 8192
#define DD       (D_MODEL * D_MODEL)

// ---------------------------------------------------------------------------
// Static scratch. fp16 2-term splits: only Q and X/AO need low parts.
// ---------------------------------------------------------------------------
__device__ __half g_QH[M_ROWS * D_MODEL];
__device__ __half g_QL[M_ROWS * D_MODEL];
__device__ __half g_KH[M_ROWS * D_MODEL];
__device__ __half g_VH[M_ROWS * D_MODEL];
__device__ __half g_XH[M_ROWS * D_MODEL];   // x, then attn-out (hi)
__device__ __half g_XL[M_ROWS * D_MODEL];   // x, then attn-out (lo)
__device__ __half g_WH[4 * DD];             // wq,wk,wv,wo hi
__device__ __half g_WL[4 * DD];             // wq,wk,wv,wo lo

// ---------------------------------------------------------------------------
// Helpers (compute_103-safe)
// ---------------------------------------------------------------------------
__device__ __forceinline__ uint32_t smem_u32(const void* p) {
    uint32_t a;
    asm("{ .reg .u64 t; cvta.to.shared.u64 t, %1; cvt.u32.u64 %0, t; }"
        : "=r"(a) : "l"(p));
    return a;
}
__device__ __forceinline__ void cp_async16(uint32_t dst, const void* src) {
    asm volatile("cp.async.cg.shared.global [%0], [%1], 16;\n"
                 :: "r"(dst), "l"(src) : "memory");
}
__device__ __forceinline__ void cp_commit() {
    asm volatile("cp.async.commit_group;\n" ::: "memory");
}
template <int N>
__device__ __forceinline__ void cp_wait() {
    asm volatile("cp.async.wait_group %0;\n" :: "n"(N) : "memory");
}
__device__ __forceinline__ void ldsm_x4(uint32_t addr, uint32_t* r) {
    asm volatile("ldmatrix.sync.aligned.m8n8.x4.shared.b16 {%0,%1,%2,%3}, [%4];\n"
                 : "=r"(r[0]), "=r"(r[1]), "=r"(r[2]), "=r"(r[3]) : "r"(addr));
}
__device__ __forceinline__ void ldsm_x4t(uint32_t addr, uint32_t* r) {
    asm volatile("ldmatrix.sync.aligned.m8n8.x4.trans.shared.b16 {%0,%1,%2,%3}, [%4];\n"
                 : "=r"(r[0]), "=r"(r[1]), "=r"(r[2]), "=r"(r[3]) : "r"(addr));
}
__device__ __forceinline__ void mma16816(float* c, const uint32_t* a,
                                         uint32_t b0, uint32_t b1) {
    asm volatile(
        "mma.sync.aligned.m16n8k16.row.col.f32.f16.f16.f32 "
        "{%0,%1,%2,%3}, {%4,%5,%6,%7}, {%8,%9}, {%0,%1,%2,%3};\n"
        : "+f"(c[0]), "+f"(c[1]), "+f"(c[2]), "+f"(c[3])
        : "r"(a[0]), "r"(a[1]), "r"(a[2]), "r"(a[3]), "r"(b0), "r"(b1));
}
// fp16 split: hi = rn(x,y), lo = rn(residual)
__device__ __forceinline__ void packsplit(float x, float y,
                                          uint32_t& hi, uint32_t& lo) {
    __half2 H = __floats2half2_rn(x, y);
    float2 Hf = __half22float2(H);
    __half2 L = __floats2half2_rn(x - Hf.x, y - Hf.y);
    hi = *(uint32_t*)&H;
    lo = *(uint32_t*)&L;
}
__device__ __forceinline__ uint32_t packhi(float x, float y) {
    __half2 H = __floats2half2_rn(x, y);
    return *(uint32_t*)&H;
}

// ---------------------------------------------------------------------------
// Split conversions for x and W
// ---------------------------------------------------------------------------
__device__ __forceinline__ void split4(float4 v, __half* h, __half* l,
                                       size_t idx4) {
    uint32_t h0, l0, h1, l1;
    packsplit(v.x, v.y, h0, l0);
    packsplit(v.z, v.w, h1, l1);
    ((uint32_t*)h)[idx4 * 2 + 0] = h0;
    ((uint32_t*)h)[idx4 * 2 + 1] = h1;
    ((uint32_t*)l)[idx4 * 2 + 0] = l0;
    ((uint32_t*)l)[idx4 * 2 + 1] = l1;
}
__global__ void conv_x(const float* __restrict__ x) {
    size_t i = (size_t)blockIdx.x * blockDim.x + threadIdx.x;
    split4(((const float4*)x)[i], g_XH, g_XL, i);
}
__global__ void conv_w(const float* __restrict__ w0, const float* __restrict__ w1,
                       const float* __restrict__ w2, const float* __restrict__ w3) {
    const float* w = (blockIdx.z == 0) ? w0 : (blockIdx.z == 1) ? w1
                   : (blockIdx.z == 2) ? w2 : w3;
    size_t i = (size_t)blockIdx.x * blockDim.x + threadIdx.x;
    split4(((const float4*)w)[i], g_WH + (size_t)blockIdx.z * DD,
           g_WL + (size_t)blockIdx.z * DD, i);
}

// ---------------------------------------------------------------------------
// 2-term split-fp16 GEMM (R7 pipeline structure): C = Ah*Bh + Al*Bh.
// BM=BN=128, BK=64, 3-stage cp.async, 8 warps, m16n8k16.
// ---------------------------------------------------------------------------
#define BK      64
#define NKT     (D_MODEL / BK)    // 16
#define NTILES  (2 * NKT)         // 32  (2 terms)
#define A_BYTES (128 * 128)       // 16384
#define STAGE   (2 * A_BYTES)     // 32768
#define SM_GEMM (3 * STAGE)       // 98304

__device__ __forceinline__ void gemm_core(const __half* __restrict__ Bh,
                                          const __half* __restrict__ Bl,
                                          float* __restrict__ Cf,
                                          __half* __restrict__ Ch,
                                          __half* __restrict__ Cl,
                                          float scl)
{
    extern __shared__ char smem[];
    const uint32_t sb = smem_u32(smem);
    const int tid = threadIdx.x;
    const int wid = tid >> 5, lid = tid & 31;
    const int wm  = wid >> 2, wn = wid & 3;
    const int bm  = blockIdx.y * 128, bn = blockIdx.x * 128;
    (void)Bl;

    const __half* At[2] = { g_XH, g_XL };   // 2 terms: Ah*Bh + Al*Bh

    const int llo  = lid & 7;
    const int lr15 = lid & 15;
    const int lhiA = lid >> 4;
    const int lk8B = (lid >> 3) & 1;
    uint32_t aRow[4], bRow[2];
#pragma unroll
    for (int i = 0; i < 4; i++) aRow[i] = (uint32_t)(wm * 64 + i * 16 + lr15) * 128;
#pragma unroll
    for (int p = 0; p < 2; p++)
        bRow[p] = A_BYTES + (uint32_t)(wn * 32 + p * 16 + llo + ((lid >> 4) & 1) * 8) * 128;

    float acc[4][4][4];
#pragma unroll
    for (int i = 0; i < 4; i++)
#pragma unroll
        for (int j = 0; j < 4; j++)
#pragma unroll
            for (int q = 0; q < 4; q++) acc[i][j][q] = 0.f;

    auto issue = [&](int t) {
        const int term = t / NKT, kt = t % NKT;
        const __half* Asrc = At[term] + (size_t)bm * D_MODEL + kt * BK;
        const __half* Bsrc = Bh       + (size_t)bn * D_MODEL + kt * BK;
        const uint32_t st = sb + (uint32_t)(t % 3) * STAGE;
#pragma unroll
        for (int u = 0; u < 8; u++) {
            const int i = tid + u * 256;
            const int which = i >> 10;
            const int j = i & 1023;
            const int r = j >> 3, c = j & 7;
            const __half* src =
                (which ? Bsrc : Asrc) + (size_t)r * D_MODEL + c * 8;
            const uint32_t dst = st + (uint32_t)which * A_BYTES +
                                 (uint32_t)r * 128 + (uint32_t)((c ^ (r & 7)) << 4);
            cp_async16(dst, src);
        }
        cp_commit();
    };

    issue(0);
    issue(1);
    issue(2);

#pragma unroll 1
    for (int t = 0; t < NTILES; t++) {
        if (t < NTILES - 2)       cp_wait<2>();
        else if (t == NTILES - 2) cp_wait<1>();
        else                      cp_wait<0>();
        __syncthreads();

        const uint32_t st = sb + (uint32_t)(t % 3) * STAGE;
#pragma unroll
        for (int s = 0; s < 4; s++) {
            const uint32_t offA = (uint32_t)(((2 * s + lhiA) ^ llo) << 4);
            const uint32_t offB = (uint32_t)(((2 * s + lk8B) ^ llo) << 4);
            uint32_t a[4][4], b[2][4];
#pragma unroll
            for (int i = 0; i < 4; i++) ldsm_x4(st + aRow[i] + offA, a[i]);
#pragma unroll
            for (int p = 0; p < 2; p++) ldsm_x4(st + bRow[p] + offB, b[p]);
#pragma unroll
            for (int i = 0; i < 4; i++)
#pragma unroll
                for (int j = 0; j < 4; j++)
                    mma16816(acc[i][j], a[i], b[j >> 1][(j & 1) * 2 + 0],
                                               b[j >> 1][(j & 1) * 2 + 1]);
        }
        __syncthreads();
        if (t + 3 < NTILES) issue(t + 3);
    }

    const int g  = lid >> 2;
    const int t2 = (lid & 3) * 2;
#pragma unroll
    for (int i = 0; i < 4; i++) {
        const int row = bm + wm * 64 + i * 16 + g;
#pragma unroll
        for (int j = 0; j < 4; j++) {
            const int col = bn + wn * 32 + j * 8 + t2;
            if (Cf) {
                *(float2*)&Cf[(size_t)row * D_MODEL + col] =
                    make_float2(acc[i][j][0], acc[i][j][1]);
                *(float2*)&Cf[(size_t)(row + 8) * D_MODEL + col] =
                    make_float2(acc[i][j][2], acc[i][j][3]);
            } else if (Cl) {    // split output (Q, AO)
                uint32_t h, l;
                packsplit(acc[i][j][0] * scl, acc[i][j][1] * scl, h, l);
                *(uint32_t*)&Ch[(size_t)row * D_MODEL + col] = h;
                *(uint32_t*)&Cl[(size_t)row * D_MODEL + col] = l;
                packsplit(acc[i][j][2] * scl, acc[i][j][3] * scl, h, l);
                *(uint32_t*)&Ch[(size_t)(row + 8) * D_MODEL + col] = h;
                *(uint32_t*)&Cl[(size_t)(row + 8) * D_MODEL + col] = l;
            } else {            // high-only output (K, V)
                *(uint32_t*)&Ch[(size_t)row * D_MODEL + col] =
                    packhi(acc[i][j][0], acc[i][j][1]);
                *(uint32_t*)&Ch[(size_t)(row + 8) * D_MODEL + col] =
                    packhi(acc[i][j][2], acc[i][j][3]);
            }
        }
    }
}

__global__ void __launch_bounds__(256, 2)
gemm_qkv() {
    const int z = blockIdx.z;
    if (z == 0)
        gemm_core(g_WH, g_WL, nullptr, g_QH, g_QL, 0.125f);   // Q split, pre-scaled
    else if (z == 1)
        gemm_core(g_WH + DD, g_WL + DD, nullptr, g_KH, nullptr, 1.f);
    else
        gemm_core(g_WH + 2ull * DD, g_WL + 2ull * DD, nullptr, g_VH, nullptr, 1.f);
}
__global__ void __launch_bounds__(256, 2)
gemm_o(float* __restrict__ out) {
    gemm_core(g_WH + 3ull * DD, g_WL + 3ull * DD, out, nullptr, nullptr, 1.f);
}

// ---------------------------------------------------------------------------
// Tensor-core causal flash attention, fp16 2-term:
// S = (Qh+Ql)·Kh ; O += (Ph+Pl)·Vh. Stage = Kh(8K)|Vh(8K)|mask(256) = 16.6KB.
// ---------------------------------------------------------------------------
#define AST 16640
#define SM_ATTN (2 * AST)    // 33280

__global__ void __launch_bounds__(128, 3)
attn_mma(const int* __restrict__ mask)
{
    extern __shared__ char smem[];
    const uint32_t sb = smem_u32(smem);
    const int tid = threadIdx.x, wid = tid >> 5, lid = tid & 31;
    const int qt = blockIdx.x, h = blockIdx.y, b = blockIdx.z;
    const int bm = qt * 64;
    const int nt = qt + 1;                // causal: key tiles 0..qt

    // ---- stage Q (QH|QL) into the two-stage area, extract fragments ----
    {
#pragma unroll
        for (int u = 0; u < 8; u++) {
            const int i = tid + u * 128;          // 0..1023
            const int arr = i >> 9;               // 0 QH, 1 QL
            const int j = i & 511;
            const int r = j >> 3, c = j & 7;
            const __half* src = (arr ? g_QL : g_QH) +
                (size_t)(b * SEQ + bm + r) * D_MODEL + h * HEAD_DIM + c * 8;
            cp_async16(sb + (uint32_t)arr * 8192 +
                       (uint32_t)r * 128 + (uint32_t)((c ^ (r & 7)) << 4), src);
        }
        cp_commit();
        cp_wait<0>();
        __syncthreads();
    }
    uint32_t aQh[4][4], aQl[4][4];
#pragma unroll
    for (int ks = 0; ks < 4; ks++) {
        const uint32_t off = (uint32_t)(wid * 16 + (lid & 15)) * 128 +
                             (uint32_t)(((2 * ks + (lid >> 4)) ^ (lid & 7)) << 4);
        ldsm_x4(sb + off, aQh[ks]);
        ldsm_x4(sb + 8192 + off, aQl[ks]);
    }
    __syncthreads();          // Q extracted; area reused for KV stages

    auto issueKV = [&](int ti) {
        const uint32_t st = sb + (uint32_t)(ti & 1) * AST;
        const int t0 = ti * 64;
#pragma unroll
        for (int u = 0; u < 8; u++) {
            const int i = tid + u * 128;          // 0..1023
            const int arr = i >> 9;               // 0 Kh, 1 Vh
            const int j = i & 511;
            const int r = j >> 3, c = j & 7;
            const __half* base = arr ? g_VH : g_KH;
            const __half* src = base +
                (size_t)(b * SEQ + t0 + r) * D_MODEL + h * HEAD_DIM + c * 8;
            cp_async16(st + (uint32_t)arr * 8192 +
                       (uint32_t)r * 128 + (uint32_t)((c ^ (r & 7)) << 4), src);
        }
        if (tid < 16)
            cp_async16(st + 16384 + tid * 16, mask + b * SEQ + t0 + tid * 4);
        cp_commit();
    };

    issueKV(0);
    if (nt > 1) issueKV(1);

    float oreg[8][4];
#pragma unroll
    for (int j = 0; j < 8; j++)
#pragma unroll
        for (int q = 0; q < 4; q++) oreg[j][q] = 0.f;
    float mA = -1e30f, mB = -1e30f, lA = 0.f, lB = 0.f;
    const int q0 = bm + wid * 16 + (lid >> 2);

#pragma unroll 1
    for (int ti = 0; ti < nt; ti++) {
        if (ti == nt - 1) cp_wait<0>(); else cp_wait<1>();
        __syncthreads();
        const uint32_t st = sb + (uint32_t)(ti & 1) * AST;
        const int* msk_s = (const int*)(smem + (ti & 1) * AST + 16384);
        const int t0 = ti * 64;

        // ---- S = (Qh + Ql) @ Kh^T ----
        float sr[8][4];
#pragma unroll
        for (int j = 0; j < 8; j++)
#pragma unroll
            for (int q = 0; q < 4; q++) sr[j][q] = 0.f;
#pragma unroll
        for (int ks = 0; ks < 4; ks++) {
            uint32_t bh[4][4];
#pragma unroll
            for (int nb = 0; nb < 4; nb++) {
                const uint32_t row = (uint32_t)(nb * 16 + (lid & 7) + ((lid >> 4) & 1) * 8);
                const uint32_t off = row * 128 +
                    (uint32_t)(((2 * ks + ((lid >> 3) & 1)) ^ (lid & 7)) << 4);
                ldsm_x4(st + off, bh[nb]);
            }
#pragma unroll
            for (int j = 0; j < 8; j++) {
                const uint32_t b0 = bh[j >> 1][(j & 1) * 2], b1 = bh[j >> 1][(j & 1) * 2 + 1];
                mma16816(sr[j], aQh[ks], b0, b1);
                mma16816(sr[j], aQl[ks], b0, b1);
            }
        }

        // ---- mask + online softmax ----
        const bool diag = (ti == qt);
#pragma unroll
        for (int j = 0; j < 8; j++) {
            const int c = j * 8 + (lid & 3) * 2;
            const int kg = t0 + c;
            const int mk0 = msk_s[c], mk1 = msk_s[c + 1];
            if (!mk0) { sr[j][0] = -1e30f; sr[j][2] = -1e30f; }
            if (!mk1) { sr[j][1] = -1e30f; sr[j][3] = -1e30f; }
            if (diag) {
                if (kg     > q0)     sr[j][0] = -1e30f;
                if (kg + 1 > q0)     sr[j][1] = -1e30f;
                if (kg     > q0 + 8) sr[j][2] = -1e30f;
                if (kg + 1 > q0 + 8) sr[j][3] = -1e30f;
            }
        }
        float tmA = -1e30f, tmB = -1e30f;
#pragma unroll
        for (int j = 0; j < 8; j++) {
            tmA = fmaxf(tmA, fmaxf(sr[j][0], sr[j][1]));
            tmB = fmaxf(tmB, fmaxf(sr[j][2], sr[j][3]));
        }
        tmA = fmaxf(tmA, __shfl_xor_sync(0xffffffff, tmA, 1));
        tmA = fmaxf(tmA, __shfl_xor_sync(0xffffffff, tmA, 2));
        tmB = fmaxf(tmB, __shfl_xor_sync(0xffffffff, tmB, 1));
        tmB = fmaxf(tmB, __shfl_xor_sync(0xffffffff, tmB, 2));
        const float nmA = fmaxf(mA, tmA), nmB = fmaxf(mB, tmB);
        const float corrA = __expf(mA - nmA), corrB = __expf(mB - nmB);
        mA = nmA; mB = nmB;
        float sA = 0.f, sB = 0.f;
#pragma unroll
        for (int j = 0; j < 8; j++) {
            sr[j][0] = __expf(sr[j][0] - nmA);
            sr[j][1] = __expf(sr[j][1] - nmA);
            sr[j][2] = __expf(sr[j][2] - nmB);
            sr[j][3] = __expf(sr[j][3] - nmB);
            sA += sr[j][0] + sr[j][1];
            sB += sr[j][2] + sr[j][3];
        }
        sA += __shfl_xor_sync(0xffffffff, sA, 1);
        sA += __shfl_xor_sync(0xffffffff, sA, 2);
        sB += __shfl_xor_sync(0xffffffff, sB, 1);
        sB += __shfl_xor_sync(0xffffffff, sB, 2);
        lA = lA * corrA + sA;
        lB = lB * corrB + sB;
#pragma unroll
        for (int j = 0; j < 8; j++) {
            oreg[j][0] *= corrA; oreg[j][1] *= corrA;
            oreg[j][2] *= corrB; oreg[j][3] *= corrB;
        }

        // ---- O += (Ph + Pl) @ Vh ----
#pragma unroll
        for (int ks = 0; ks < 4; ks++) {
            uint32_t aph[4], apl[4];
            packsplit(sr[2*ks][0],   sr[2*ks][1],   aph[0], apl[0]);
            packsplit(sr[2*ks][2],   sr[2*ks][3],   aph[1], apl[1]);
            packsplit(sr[2*ks+1][0], sr[2*ks+1][1], aph[2], apl[2]);
            packsplit(sr[2*ks+1][2], sr[2*ks+1][3], aph[3], apl[3]);
            uint32_t vh[4][4];
#pragma unroll
            for (int nb = 0; nb < 4; nb++) {
                const uint32_t row = (uint32_t)(ks * 16 + (lid & 7) + ((lid >> 3) & 1) * 8);
                const uint32_t chk = (uint32_t)(nb * 2 + (lid >> 4));
                const uint32_t off = row * 128 + ((chk ^ (lid & 7)) << 4);
                ldsm_x4t(st + 8192 + off, vh[nb]);
            }
#pragma unroll
            for (int j = 0; j < 8; j++) {
                const uint32_t b0 = vh[j >> 1][(j & 1) * 2], b1 = vh[j >> 1][(j & 1) * 2 + 1];
                mma16816(oreg[j], aph, b0, b1);
                mma16816(oreg[j], apl, b0, b1);
            }
        }

        __syncthreads();
        if (ti + 2 < nt) issueKV(ti + 2);
    }

    // ---- epilogue: normalize, split to fp16 h/l for the O-GEMM ----
    const float invA = 1.f / lA, invB = 1.f / lB;
    const size_t rA = (size_t)(b * SEQ + q0) * D_MODEL + h * HEAD_DIM;
    const size_t rB = rA + 8ull * D_MODEL;
#pragma unroll
    for (int j = 0; j < 8; j++) {
        const int col = j * 8 + (lid & 3) * 2;
        uint32_t hh, ll;
        packsplit(oreg[j][0] * invA, oreg[j][1] * invA, hh, ll);
        *(uint32_t*)&g_XH[rA + col] = hh;
        *(uint32_t*)&g_XL[rA + col] = ll;
        packsplit(oreg[j][2] * invB, oreg[j][3] * invB, hh, ll);
        *(uint32_t*)&g_XH[rB + col] = hh;
        *(uint32_t*)&g_XL[rB + col] = ll;
    }
}

// ---------------------------------------------------------------------------
// Launch. Inputs: x, attention_mask, wq, wk, wv, wo. Output fp32.
// ---------------------------------------------------------------------------
extern "C" void kernel_launch(void* const* d_in, const int* in_sizes, int n_in,
                              void* d_out, int out_size)
{
    const float* x    = (const float*)d_in[0];
    const int*   amsk = (const int*)  d_in[1];
    const float* wq   = (const float*)d_in[2];
    const float* wk   = (const float*)d_in[3];
    const float* wv   = (const float*)d_in[4];
    const float* wo   = (const float*)d_in[5];
    float*       out  = (float*)d_out;

    cudaFuncSetAttribute(gemm_qkv, cudaFuncAttributeMaxDynamicSharedMemorySize, SM_GEMM);
    cudaFuncSetAttribute(gemm_o,   cudaFuncAttributeMaxDynamicSharedMemorySize, SM_GEMM);
    cudaFuncSetAttribute(attn_mma, cudaFuncAttributeMaxDynamicSharedMemorySize, SM_ATTN);

    conv_x<<<M_ROWS * D_MODEL / 4 / 256, 256>>>(x);
    conv_w<<<dim3(DD / 4 / 256, 1, 4), 256>>>(wq, wk, wv, wo);

    dim3 gQKV(D_MODEL / 128, M_ROWS / 128, 3);   // (8, 64, 3)
    gemm_qkv<<<gQKV, 256, SM_GEMM>>>();

    dim3 gAttn(SEQ / 64, N_HEADS, BATCH);        // (32, 16, 4)
    attn_mma<<<gAttn, 128, SM_ATTN>>>(amsk);

    dim3 gOut(D_MODEL / 128, M_ROWS / 128, 1);
    gemm_o<<<gOut, 256, SM_GEMM>>>(out);
}

// round 10
// speedup vs baseline: 2.2232x; 1.0106x over previous
#include <cuda_runtime.h>
#include <cuda_fp16.h>
#include <cstdint>
#include <math.h>

#define D_MODEL  1024
#define N_HEADS  16
#define HEAD_DIM 64
#define BATCH    4
#define SEQ      2048
#define M_ROWS   (BATCH * SEQ)   // 8192
#define DD       (D_MODEL * D_MODEL)

// ---------------------------------------------------------------------------
// Static scratch. fp16 2-term splits: only Q and X/AO need low parts.
// ---------------------------------------------------------------------------
__device__ __half g_QH[M_ROWS * D_MODEL];
__device__ __half g_QL[M_ROWS * D_MODEL];
__device__ __half g_KH[M_ROWS * D_MODEL];
__device__ __half g_VH[M_ROWS * D_MODEL];
__device__ __half g_XH[M_ROWS * D_MODEL];   // x, then attn-out (hi)
__device__ __half g_XL[M_ROWS * D_MODEL];   // x, then attn-out (lo)
__device__ __half g_WH[4 * DD];             // wq,wk,wv,wo hi
__device__ __half g_WL[4 * DD];             // wq,wk,wv,wo lo

// ---------------------------------------------------------------------------
// Helpers (compute_103-safe)
// ---------------------------------------------------------------------------
__device__ __forceinline__ uint32_t smem_u32(const void* p) {
    uint32_t a;
    asm("{ .reg .u64 t; cvta.to.shared.u64 t, %1; cvt.u32.u64 %0, t; }"
        : "=r"(a) : "l"(p));
    return a;
}
__device__ __forceinline__ void cp_async16(uint32_t dst, const void* src) {
    asm volatile("cp.async.cg.shared.global [%0], [%1], 16;\n"
                 :: "r"(dst), "l"(src) : "memory");
}
__device__ __forceinline__ void cp_commit() {
    asm volatile("cp.async.commit_group;\n" ::: "memory");
}
template <int N>
__device__ __forceinline__ void cp_wait() {
    asm volatile("cp.async.wait_group %0;\n" :: "n"(N) : "memory");
}
__device__ __forceinline__ void ldsm_x4(uint32_t addr, uint32_t* r) {
    asm volatile("ldmatrix.sync.aligned.m8n8.x4.shared.b16 {%0,%1,%2,%3}, [%4];\n"
                 : "=r"(r[0]), "=r"(r[1]), "=r"(r[2]), "=r"(r[3]) : "r"(addr));
}
__device__ __forceinline__ void ldsm_x4t(uint32_t addr, uint32_t* r) {
    asm volatile("ldmatrix.sync.aligned.m8n8.x4.trans.shared.b16 {%0,%1,%2,%3}, [%4];\n"
                 : "=r"(r[0]), "=r"(r[1]), "=r"(r[2]), "=r"(r[3]) : "r"(addr));
}
__device__ __forceinline__ void mma16816(float* c, const uint32_t* a,
                                         uint32_t b0, uint32_t b1) {
    asm volatile(
        "mma.sync.aligned.m16n8k16.row.col.f32.f16.f16.f32 "
        "{%0,%1,%2,%3}, {%4,%5,%6,%7}, {%8,%9}, {%0,%1,%2,%3};\n"
        : "+f"(c[0]), "+f"(c[1]), "+f"(c[2]), "+f"(c[3])
        : "r"(a[0]), "r"(a[1]), "r"(a[2]), "r"(a[3]), "r"(b0), "r"(b1));
}
__device__ __forceinline__ void packsplit(float x, float y,
                                          uint32_t& hi, uint32_t& lo) {
    __half2 H = __floats2half2_rn(x, y);
    float2 Hf = __half22float2(H);
    __half2 L = __floats2half2_rn(x - Hf.x, y - Hf.y);
    hi = *(uint32_t*)&H;
    lo = *(uint32_t*)&L;
}
__device__ __forceinline__ uint32_t packhi(float x, float y) {
    __half2 H = __floats2half2_rn(x, y);
    return *(uint32_t*)&H;
}

// ---------------------------------------------------------------------------
// Merged split conversion: z 0..3 -> quarters of x, z=4 -> wq|wk, z=5 -> wv|wo
// ---------------------------------------------------------------------------
__device__ __forceinline__ void split4(float4 v, __half* h, __half* l,
                                       size_t idx4) {
    uint32_t h0, l0, h1, l1;
    packsplit(v.x, v.y, h0, l0);
    packsplit(v.z, v.w, h1, l1);
    ((uint32_t*)h)[idx4 * 2 + 0] = h0;
    ((uint32_t*)h)[idx4 * 2 + 1] = h1;
    ((uint32_t*)l)[idx4 * 2 + 0] = l0;
    ((uint32_t*)l)[idx4 * 2 + 1] = l1;
}
__global__ void conv_all(const float* __restrict__ x,
                         const float* __restrict__ w0, const float* __restrict__ w1,
                         const float* __restrict__ w2, const float* __restrict__ w3)
{
    const int z = blockIdx.z;
    const size_t bx = blockIdx.x;                      // 0..2047
    const size_t li = bx * blockDim.x + threadIdx.x;   // 0..524287 (float4 idx)
    if (z < 4) {
        const size_t i = (size_t)z * 524288 + li;      // x: 2M float4 total
        split4(((const float4*)x)[i], g_XH, g_XL, i);
    } else {
        const int wsel = (z - 4) * 2 + (int)(li >> 18);    // 0..3
        const size_t i = li & 262143;                      // DD/4 = 262144
        const float* w = (wsel == 0) ? w0 : (wsel == 1) ? w1
                       : (wsel == 2) ? w2 : w3;
        split4(((const float4*)w)[i], g_WH + (size_t)wsel * DD,
               g_WL + (size_t)wsel * DD, i);
    }
}

// ---------------------------------------------------------------------------
// 2-term split-fp16 GEMM (R9, proven): C = Ah*Bh + Al*Bh.
// BM=BN=128, BK=64, 3-stage cp.async, 8 warps, m16n8k16.
// ---------------------------------------------------------------------------
#define BK      64
#define NKT     (D_MODEL / BK)    // 16
#define NTILES  (2 * NKT)         // 32  (2 terms)
#define A_BYTES (128 * 128)       // 16384
#define STAGE   (2 * A_BYTES)     // 32768
#define SM_GEMM (3 * STAGE)       // 98304

__device__ __forceinline__ void gemm_core(const __half* __restrict__ Bh,
                                          float* __restrict__ Cf,
                                          __half* __restrict__ Ch,
                                          __half* __restrict__ Cl,
                                          float scl)
{
    extern __shared__ char smem[];
    const uint32_t sb = smem_u32(smem);
    const int tid = threadIdx.x;
    const int wid = tid >> 5, lid = tid & 31;
    const int wm  = wid >> 2, wn = wid & 3;
    const int bm  = blockIdx.y * 128, bn = blockIdx.x * 128;

    const __half* At[2] = { g_XH, g_XL };   // 2 terms: Ah*Bh + Al*Bh

    const int llo  = lid & 7;
    const int lr15 = lid & 15;
    const int lhiA = lid >> 4;
    const int lk8B = (lid >> 3) & 1;
    uint32_t aRow[4], bRow[2];
#pragma unroll
    for (int i = 0; i < 4; i++) aRow[i] = (uint32_t)(wm * 64 + i * 16 + lr15) * 128;
#pragma unroll
    for (int p = 0; p < 2; p++)
        bRow[p] = A_BYTES + (uint32_t)(wn * 32 + p * 16 + llo + ((lid >> 4) & 1) * 8) * 128;

    float acc[4][4][4];
#pragma unroll
    for (int i = 0; i < 4; i++)
#pragma unroll
        for (int j = 0; j < 4; j++)
#pragma unroll
            for (int q = 0; q < 4; q++) acc[i][j][q] = 0.f;

    auto issue = [&](int t) {
        const int term = t / NKT, kt = t % NKT;
        const __half* Asrc = At[term] + (size_t)bm * D_MODEL + kt * BK;
        const __half* Bsrc = Bh       + (size_t)bn * D_MODEL + kt * BK;
        const uint32_t st = sb + (uint32_t)(t % 3) * STAGE;
#pragma unroll
        for (int u = 0; u < 8; u++) {
            const int i = tid + u * 256;
            const int which = i >> 10;
            const int j = i & 1023;
            const int r = j >> 3, c = j & 7;
            const __half* src =
                (which ? Bsrc : Asrc) + (size_t)r * D_MODEL + c * 8;
            const uint32_t dst = st + (uint32_t)which * A_BYTES +
                                 (uint32_t)r * 128 + (uint32_t)((c ^ (r & 7)) << 4);
            cp_async16(dst, src);
        }
        cp_commit();
    };

    issue(0);
    issue(1);
    issue(2);

#pragma unroll 1
    for (int t = 0; t < NTILES; t++) {
        if (t < NTILES - 2)       cp_wait<2>();
        else if (t == NTILES - 2) cp_wait<1>();
        else                      cp_wait<0>();
        __syncthreads();

        const uint32_t st = sb + (uint32_t)(t % 3) * STAGE;
#pragma unroll
        for (int s = 0; s < 4; s++) {
            const uint32_t offA = (uint32_t)(((2 * s + lhiA) ^ llo) << 4);
            const uint32_t offB = (uint32_t)(((2 * s + lk8B) ^ llo) << 4);
            uint32_t a[4][4], b[2][4];
#pragma unroll
            for (int i = 0; i < 4; i++) ldsm_x4(st + aRow[i] + offA, a[i]);
#pragma unroll
            for (int p = 0; p < 2; p++) ldsm_x4(st + bRow[p] + offB, b[p]);
#pragma unroll
            for (int i = 0; i < 4; i++)
#pragma unroll
                for (int j = 0; j < 4; j++)
                    mma16816(acc[i][j], a[i], b[j >> 1][(j & 1) * 2 + 0],
                                               b[j >> 1][(j & 1) * 2 + 1]);
        }
        __syncthreads();
        if (t + 3 < NTILES) issue(t + 3);
    }

    const int g  = lid >> 2;
    const int t2 = (lid & 3) * 2;
#pragma unroll
    for (int i = 0; i < 4; i++) {
        const int row = bm + wm * 64 + i * 16 + g;
#pragma unroll
        for (int j = 0; j < 4; j++) {
            const int col = bn + wn * 32 + j * 8 + t2;
            if (Cf) {
                *(float2*)&Cf[(size_t)row * D_MODEL + col] =
                    make_float2(acc[i][j][0], acc[i][j][1]);
                *(float2*)&Cf[(size_t)(row + 8) * D_MODEL + col] =
                    make_float2(acc[i][j][2], acc[i][j][3]);
            } else if (Cl) {    // split output (Q)
                uint32_t h, l;
                packsplit(acc[i][j][0] * scl, acc[i][j][1] * scl, h, l);
                *(uint32_t*)&Ch[(size_t)row * D_MODEL + col] = h;
                *(uint32_t*)&Cl[(size_t)row * D_MODEL + col] = l;
                packsplit(acc[i][j][2] * scl, acc[i][j][3] * scl, h, l);
                *(uint32_t*)&Ch[(size_t)(row + 8) * D_MODEL + col] = h;
                *(uint32_t*)&Cl[(size_t)(row + 8) * D_MODEL + col] = l;
            } else {            // high-only output (K, V)
                *(uint32_t*)&Ch[(size_t)row * D_MODEL + col] =
                    packhi(acc[i][j][0], acc[i][j][1]);
                *(uint32_t*)&Ch[(size_t)(row + 8) * D_MODEL + col] =
                    packhi(acc[i][j][2], acc[i][j][3]);
            }
        }
    }
}

__global__ void __launch_bounds__(256, 2)
gemm_qkv() {
    const int z = blockIdx.z;
    if (z == 0)
        gemm_core(g_WH, nullptr, g_QH, g_QL, 0.125f);   // Q split, pre-scaled
    else if (z == 1)
        gemm_core(g_WH + DD, nullptr, g_KH, nullptr, 1.f);
    else
        gemm_core(g_WH + 2ull * DD, nullptr, g_VH, nullptr, 1.f);
}
__global__ void __launch_bounds__(256, 2)
gemm_o(float* __restrict__ out) {
    gemm_core(g_WH + 3ull * DD, out, nullptr, nullptr, 1.f);
}

// ---------------------------------------------------------------------------
// Tensor-core causal flash attention, fp16 2-term.
// S = (Qh+Ql)·Kh ; O += (Ph+Pl)·Vh. 3-stage KV pipeline; LPT block order.
// Stage = Kh(8K)|Vh(8K)|mask(256) = 16.6KB; 3 stages ~50KB; 3 blocks/SM.
// ---------------------------------------------------------------------------
#define AST 16640
#define SM_ATTN (3 * AST)    // 49920

__global__ void __launch_bounds__(128, 3)
attn_mma(const int* __restrict__ mask)
{
    extern __shared__ char smem[];
    const uint32_t sb = smem_u32(smem);
    const int tid = threadIdx.x, wid = tid >> 5, lid = tid & 31;
    const int qt = gridDim.x - 1 - blockIdx.x;      // LPT: heavy blocks first
    const int h = blockIdx.y, b = blockIdx.z;
    const int bm = qt * 64;
    const int nt = qt + 1;                // causal: key tiles 0..qt

    // ---- stage Q (QH|QL) into the stage area, extract fragments ----
    {
#pragma unroll
        for (int u = 0; u < 8; u++) {
            const int i = tid + u * 128;          // 0..1023
            const int arr = i >> 9;               // 0 QH, 1 QL
            const int j = i & 511;
            const int r = j >> 3, c = j & 7;
            const __half* src = (arr ? g_QL : g_QH) +
                (size_t)(b * SEQ + bm + r) * D_MODEL + h * HEAD_DIM + c * 8;
            cp_async16(sb + (uint32_t)arr * 8192 +
                       (uint32_t)r * 128 + (uint32_t)((c ^ (r & 7)) << 4), src);
        }
        cp_commit();
        cp_wait<0>();
        __syncthreads();
    }
    uint32_t aQh[4][4], aQl[4][4];
#pragma unroll
    for (int ks = 0; ks < 4; ks++) {
        const uint32_t off = (uint32_t)(wid * 16 + (lid & 15)) * 128 +
                             (uint32_t)(((2 * ks + (lid >> 4)) ^ (lid & 7)) << 4);
        ldsm_x4(sb + off, aQh[ks]);
        ldsm_x4(sb + 8192 + off, aQl[ks]);
    }
    __syncthreads();          // Q extracted; area reused for KV stages

    auto issueKV = [&](int ti) {
        const uint32_t st = sb + (uint32_t)(ti % 3) * AST;
        const int t0 = ti * 64;
#pragma unroll
        for (int u = 0; u < 8; u++) {
            const int i = tid + u * 128;          // 0..1023
            const int arr = i >> 9;               // 0 Kh, 1 Vh
            const int j = i & 511;
            const int r = j >> 3, c = j & 7;
            const __half* base = arr ? g_VH : g_KH;
            const __half* src = base +
                (size_t)(b * SEQ + t0 + r) * D_MODEL + h * HEAD_DIM + c * 8;
            cp_async16(st + (uint32_t)arr * 8192 +
                       (uint32_t)r * 128 + (uint32_t)((c ^ (r & 7)) << 4), src);
        }
        if (tid < 16)
            cp_async16(st + 16384 + tid * 16, mask + b * SEQ + t0 + tid * 4);
        cp_commit();
    };

    issueKV(0);
    if (nt > 1) issueKV(1);
    if (nt > 2) issueKV(2);

    float oreg[8][4];
#pragma unroll
    for (int j = 0; j < 8; j++)
#pragma unroll
        for (int q = 0; q < 4; q++) oreg[j][q] = 0.f;
    float mA = -1e30f, mB = -1e30f, lA = 0.f, lB = 0.f;
    const int q0 = bm + wid * 16 + (lid >> 2);

#pragma unroll 1
    for (int ti = 0; ti < nt; ti++) {
        const int rem = nt - ti;
        if (rem > 2)      cp_wait<2>();
        else if (rem == 2) cp_wait<1>();
        else               cp_wait<0>();
        __syncthreads();
        const uint32_t st = sb + (uint32_t)(ti % 3) * AST;
        const int* msk_s = (const int*)(smem + (ti % 3) * AST + 16384);
        const int t0 = ti * 64;

        // ---- S = (Qh + Ql) @ Kh^T ----
        float sr[8][4];
#pragma unroll
        for (int j = 0; j < 8; j++)
#pragma unroll
            for (int q = 0; q < 4; q++) sr[j][q] = 0.f;
#pragma unroll
        for (int ks = 0; ks < 4; ks++) {
            uint32_t bh[4][4];
#pragma unroll
            for (int nb = 0; nb < 4; nb++) {
                const uint32_t row = (uint32_t)(nb * 16 + (lid & 7) + ((lid >> 4) & 1) * 8);
                const uint32_t off = row * 128 +
                    (uint32_t)(((2 * ks + ((lid >> 3) & 1)) ^ (lid & 7)) << 4);
                ldsm_x4(st + off, bh[nb]);
            }
#pragma unroll
            for (int j = 0; j < 8; j++) {
                const uint32_t b0 = bh[j >> 1][(j & 1) * 2], b1 = bh[j >> 1][(j & 1) * 2 + 1];
                mma16816(sr[j], aQh[ks], b0, b1);
                mma16816(sr[j], aQl[ks], b0, b1);
            }
        }

        // ---- mask + online softmax ----
        const bool diag = (ti == qt);
#pragma unroll
        for (int j = 0; j < 8; j++) {
            const int c = j * 8 + (lid & 3) * 2;
            const int kg = t0 + c;
            const int mk0 = msk_s[c], mk1 = msk_s[c + 1];
            if (!mk0) { sr[j][0] = -1e30f; sr[j][2] = -1e30f; }
            if (!mk1) { sr[j][1] = -1e30f; sr[j][3] = -1e30f; }
            if (diag) {
                if (kg     > q0)     sr[j][0] = -1e30f;
                if (kg + 1 > q0)     sr[j][1] = -1e30f;
                if (kg     > q0 + 8) sr[j][2] = -1e30f;
                if (kg + 1 > q0 + 8) sr[j][3] = -1e30f;
            }
        }
        float tmA = -1e30f, tmB = -1e30f;
#pragma unroll
        for (int j = 0; j < 8; j++) {
            tmA = fmaxf(tmA, fmaxf(sr[j][0], sr[j][1]));
            tmB = fmaxf(tmB, fmaxf(sr[j][2], sr[j][3]));
        }
        tmA = fmaxf(tmA, __shfl_xor_sync(0xffffffff, tmA, 1));
        tmA = fmaxf(tmA, __shfl_xor_sync(0xffffffff, tmA, 2));
        tmB = fmaxf(tmB, __shfl_xor_sync(0xffffffff, tmB, 1));
        tmB = fmaxf(tmB, __shfl_xor_sync(0xffffffff, tmB, 2));
        const float nmA = fmaxf(mA, tmA), nmB = fmaxf(mB, tmB);
        const float corrA = __expf(mA - nmA), corrB = __expf(mB - nmB);
        mA = nmA; mB = nmB;
        float sA = 0.f, sB = 0.f;
#pragma unroll
        for (int j = 0; j < 8; j++) {
            sr[j][0] = __expf(sr[j][0] - nmA);
            sr[j][1] = __expf(sr[j][1] - nmA);
            sr[j][2] = __expf(sr[j][2] - nmB);
            sr[j][3] = __expf(sr[j][3] - nmB);
            sA += sr[j][0] + sr[j][1];
            sB += sr[j][2] + sr[j][3];
        }
        sA += __shfl_xor_sync(0xffffffff, sA, 1);
        sA += __shfl_xor_sync(0xffffffff, sA, 2);
        sB += __shfl_xor_sync(0xffffffff, sB, 1);
        sB += __shfl_xor_sync(0xffffffff, sB, 2);
        lA = lA * corrA + sA;
        lB = lB * corrB + sB;
#pragma unroll
        for (int j = 0; j < 8; j++) {
            oreg[j][0] *= corrA; oreg[j][1] *= corrA;
            oreg[j][2] *= corrB; oreg[j][3] *= corrB;
        }

        // ---- O += (Ph + Pl) @ Vh ----
#pragma unroll
        for (int ks = 0; ks < 4; ks++) {
            uint32_t aph[4], apl[4];
            packsplit(sr[2*ks][0],   sr[2*ks][1],   aph[0], apl[0]);
            packsplit(sr[2*ks][2],   sr[2*ks][3],   aph[1], apl[1]);
            packsplit(sr[2*ks+1][0], sr[2*ks+1][1], aph[2], apl[2]);
            packsplit(sr[2*ks+1][2], sr[2*ks+1][3], aph[3], apl[3]);
            uint32_t vh[4][4];
#pragma unroll
            for (int nb = 0; nb < 4; nb++) {
                const uint32_t row = (uint32_t)(ks * 16 + (lid & 7) + ((lid >> 3) & 1) * 8);
                const uint32_t chk = (uint32_t)(nb * 2 + (lid >> 4));
                const uint32_t off = row * 128 + ((chk ^ (lid & 7)) << 4);
                ldsm_x4t(st + 8192 + off, vh[nb]);
            }
#pragma unroll
            for (int j = 0; j < 8; j++) {
                const uint32_t b0 = vh[j >> 1][(j & 1) * 2], b1 = vh[j >> 1][(j & 1) * 2 + 1];
                mma16816(oreg[j], aph, b0, b1);
                mma16816(oreg[j], apl, b0, b1);
            }
        }

        __syncthreads();
        if (ti + 3 < nt) issueKV(ti + 3);
    }

    // ---- epilogue: normalize, split to fp16 h/l for the O-GEMM ----
    const float invA = 1.f / lA, invB = 1.f / lB;
    const size_t rA = (size_t)(b * SEQ + q0) * D_MODEL + h * HEAD_DIM;
    const size_t rB = rA + 8ull * D_MODEL;
#pragma unroll
    for (int j = 0; j < 8; j++) {
        const int col = j * 8 + (lid & 3) * 2;
        uint32_t hh, ll;
        packsplit(oreg[j][0] * invA, oreg[j][1] * invA, hh, ll);
        *(uint32_t*)&g_XH[rA + col] = hh;
        *(uint32_t*)&g_XL[rA + col] = ll;
        packsplit(oreg[j][2] * invB, oreg[j][3] * invB, hh, ll);
        *(uint32_t*)&g_XH[rB + col] = hh;
        *(uint32_t*)&g_XL[rB + col] = ll;
    }
}

// ---------------------------------------------------------------------------
// Launch. Inputs: x, attention_mask, wq, wk, wv, wo. Output fp32.
// ---------------------------------------------------------------------------
extern "C" void kernel_launch(void* const* d_in, const int* in_sizes, int n_in,
                              void* d_out, int out_size)
{
    const float* x    = (const float*)d_in[0];
    const int*   amsk = (const int*)  d_in[1];
    const float* wq   = (const float*)d_in[2];
    const float* wk   = (const float*)d_in[3];
    const float* wv   = (const float*)d_in[4];
    const float* wo   = (const float*)d_in[5];
    float*       out  = (float*)d_out;

    cudaFuncSetAttribute(gemm_qkv, cudaFuncAttributeMaxDynamicSharedMemorySize, SM_GEMM);
    cudaFuncSetAttribute(gemm_o,   cudaFuncAttributeMaxDynamicSharedMemorySize, SM_GEMM);
    cudaFuncSetAttribute(attn_mma, cudaFuncAttributeMaxDynamicSharedMemorySize, SM_ATTN);

    conv_all<<<dim3(2048, 1, 6), 256>>>(x, wq, wk, wv, wo);

    dim3 gQKV(D_MODEL / 128, M_ROWS / 128, 3);   // (8, 64, 3)
    gemm_qkv<<<gQKV, 256, SM_GEMM>>>();

    dim3 gAttn(SEQ / 64, N_HEADS, BATCH);        // (32, 16, 4)
    attn_mma<<<gAttn, 128, SM_ATTN>>>(amsk);

    dim3 gOut(D_MODEL / 128, M_ROWS / 128, 1);
    gemm_o<<<gOut, 256, SM_GEMM>>>(out);
}

// round 11
// speedup vs baseline: 2.3106x; 1.0393x over previous
#include <cuda_runtime.h>
#include <cuda_fp16.h>
#include <cstdint>
#include <math.h>

#define D_MODEL  1024
#define N_HEADS  16
#define HEAD_DIM 64
#define BATCH    4
#define SEQ      2048
#define M_ROWS   (BATCH * SEQ)   // 8192
#define DD       (D_MODEL * D_MODEL)

// ---------------------------------------------------------------------------
// Static scratch. fp16 2-term splits: only Q and X/AO need low parts.
// ---------------------------------------------------------------------------
__device__ __half g_QH[M_ROWS * D_MODEL];
__device__ __half g_QL[M_ROWS * D_MODEL];
__device__ __half g_KH[M_ROWS * D_MODEL];
__device__ __half g_VH[M_ROWS * D_MODEL];
__device__ __half g_XH[M_ROWS * D_MODEL];   // x, then attn-out (hi)
__device__ __half g_XL[M_ROWS * D_MODEL];   // x, then attn-out (lo)
__device__ __half g_WH[4 * DD];             // wq,wk,wv,wo hi
__device__ __half g_WL[4 * DD];             // wq,wk,wv,wo lo

// ---------------------------------------------------------------------------
// Helpers (compute_103-safe)
// ---------------------------------------------------------------------------
__device__ __forceinline__ uint32_t smem_u32(const void* p) {
    uint32_t a;
    asm("{ .reg .u64 t; cvta.to.shared.u64 t, %1; cvt.u32.u64 %0, t; }"
        : "=r"(a) : "l"(p));
    return a;
}
__device__ __forceinline__ void cp_async16(uint32_t dst, const void* src) {
    asm volatile("cp.async.cg.shared.global [%0], [%1], 16;\n"
                 :: "r"(dst), "l"(src) : "memory");
}
__device__ __forceinline__ void cp_commit() {
    asm volatile("cp.async.commit_group;\n" ::: "memory");
}
template <int N>
__device__ __forceinline__ void cp_wait() {
    asm volatile("cp.async.wait_group %0;\n" :: "n"(N) : "memory");
}
__device__ __forceinline__ void ldsm_x4(uint32_t addr, uint32_t* r) {
    asm volatile("ldmatrix.sync.aligned.m8n8.x4.shared.b16 {%0,%1,%2,%3}, [%4];\n"
                 : "=r"(r[0]), "=r"(r[1]), "=r"(r[2]), "=r"(r[3]) : "r"(addr));
}
__device__ __forceinline__ void ldsm_x4t(uint32_t addr, uint32_t* r) {
    asm volatile("ldmatrix.sync.aligned.m8n8.x4.trans.shared.b16 {%0,%1,%2,%3}, [%4];\n"
                 : "=r"(r[0]), "=r"(r[1]), "=r"(r[2]), "=r"(r[3]) : "r"(addr));
}
__device__ __forceinline__ void mma16816(float* c, const uint32_t* a,
                                         uint32_t b0, uint32_t b1) {
    asm volatile(
        "mma.sync.aligned.m16n8k16.row.col.f32.f16.f16.f32 "
        "{%0,%1,%2,%3}, {%4,%5,%6,%7}, {%8,%9}, {%0,%1,%2,%3};\n"
        : "+f"(c[0]), "+f"(c[1]), "+f"(c[2]), "+f"(c[3])
        : "r"(a[0]), "r"(a[1]), "r"(a[2]), "r"(a[3]), "r"(b0), "r"(b1));
}
__device__ __forceinline__ void packsplit(float x, float y,
                                          uint32_t& hi, uint32_t& lo) {
    __half2 H = __floats2half2_rn(x, y);
    float2 Hf = __half22float2(H);
    __half2 L = __floats2half2_rn(x - Hf.x, y - Hf.y);
    hi = *(uint32_t*)&H;
    lo = *(uint32_t*)&L;
}
__device__ __forceinline__ uint32_t packhi(float x, float y) {
    __half2 H = __floats2half2_rn(x, y);
    return *(uint32_t*)&H;
}

// ---------------------------------------------------------------------------
// Merged split conversion: z 0..3 -> quarters of x, z=4 -> wq|wk, z=5 -> wv|wo
// ---------------------------------------------------------------------------
__device__ __forceinline__ void split4(float4 v, __half* h, __half* l,
                                       size_t idx4) {
    uint32_t h0, l0, h1, l1;
    packsplit(v.x, v.y, h0, l0);
    packsplit(v.z, v.w, h1, l1);
    ((uint32_t*)h)[idx4 * 2 + 0] = h0;
    ((uint32_t*)h)[idx4 * 2 + 1] = h1;
    ((uint32_t*)l)[idx4 * 2 + 0] = l0;
    ((uint32_t*)l)[idx4 * 2 + 1] = l1;
}
__global__ void conv_all(const float* __restrict__ x,
                         const float* __restrict__ w0, const float* __restrict__ w1,
                         const float* __restrict__ w2, const float* __restrict__ w3)
{
    const int z = blockIdx.z;
    const size_t bx = blockIdx.x;                      // 0..2047
    const size_t li = bx * blockDim.x + threadIdx.x;   // 0..524287 (float4 idx)
    if (z < 4) {
        const size_t i = (size_t)z * 524288 + li;      // x: 2M float4 total
        split4(((const float4*)x)[i], g_XH, g_XL, i);
    } else {
        const int wsel = (z - 4) * 2 + (int)(li >> 18);    // 0..3
        const size_t i = li & 262143;                      // DD/4 = 262144
        const float* w = (wsel == 0) ? w0 : (wsel == 1) ? w1
                       : (wsel == 2) ? w2 : w3;
        split4(((const float4*)w)[i], g_WH + (size_t)wsel * DD,
               g_WL + (size_t)wsel * DD, i);
    }
}

// ---------------------------------------------------------------------------
// Fused 2-term split-fp16 GEMM: per k-tile stage Ah|Al|B once, run both
// term MMA sets (Ah*B then Al*B). BK=64, 2-stage cp.async, 16 iterations.
// Stage = 48KB (Ah 16K | Al 16K | B 16K); 2 stages = 96KB; 2 CTAs/SM.
// ---------------------------------------------------------------------------
#define BK      64
#define NKT     (D_MODEL / BK)    // 16
#define A_BYTES (128 * 128)       // 16384
#define STAGE   (3 * A_BYTES)     // 49152
#define SM_GEMM (2 * STAGE)       // 98304

__device__ __forceinline__ void gemm_core(const __half* __restrict__ Bh,
                                          float* __restrict__ Cf,
                                          __half* __restrict__ Ch,
                                          __half* __restrict__ Cl,
                                          float scl)
{
    extern __shared__ char smem[];
    const uint32_t sb = smem_u32(smem);
    const int tid = threadIdx.x;
    const int wid = tid >> 5, lid = tid & 31;
    const int wm  = wid >> 2, wn = wid & 3;
    const int bm  = blockIdx.y * 128, bn = blockIdx.x * 128;

    const int llo  = lid & 7;
    const int lr15 = lid & 15;
    const int lhiA = lid >> 4;
    const int lk8B = (lid >> 3) & 1;
    uint32_t aRow[4], bRow[2];
#pragma unroll
    for (int i = 0; i < 4; i++) aRow[i] = (uint32_t)(wm * 64 + i * 16 + lr15) * 128;
#pragma unroll
    for (int p = 0; p < 2; p++)
        bRow[p] = (uint32_t)(wn * 32 + p * 16 + llo + ((lid >> 4) & 1) * 8) * 128;

    float acc[4][4][4];
#pragma unroll
    for (int i = 0; i < 4; i++)
#pragma unroll
        for (int j = 0; j < 4; j++)
#pragma unroll
            for (int q = 0; q < 4; q++) acc[i][j][q] = 0.f;

    // per k-tile: stage Ah | Al | B (each 1024 x 16B chunks), 12 chunks/thread
    auto issue = [&](int kt) {
        const uint32_t st = sb + (uint32_t)(kt & 1) * STAGE;
        const int k0 = kt * BK;
#pragma unroll
        for (int u = 0; u < 12; u++) {
            const int i = tid + u * 256;              // 0..3071
            const int arr = i >> 10;                  // 0 Ah, 1 Al, 2 B
            const int j = i & 1023;
            const int r = j >> 3, c = j & 7;
            const __half* src =
                (arr == 0) ? g_XH + (size_t)(bm + r) * D_MODEL + k0 + c * 8
              : (arr == 1) ? g_XL + (size_t)(bm + r) * D_MODEL + k0 + c * 8
                           : Bh   + (size_t)(bn + r) * D_MODEL + k0 + c * 8;
            const uint32_t dst = st + (uint32_t)arr * A_BYTES +
                                 (uint32_t)r * 128 + (uint32_t)((c ^ (r & 7)) << 4);
            cp_async16(dst, src);
        }
        cp_commit();
    };

    issue(0);
    issue(1);

#pragma unroll 1
    for (int t = 0; t < NKT; t++) {
        if (t == NKT - 1) cp_wait<0>(); else cp_wait<1>();
        __syncthreads();

        const uint32_t st = sb + (uint32_t)(t & 1) * STAGE;
#pragma unroll
        for (int s = 0; s < 4; s++) {
            const uint32_t offA = (uint32_t)(((2 * s + lhiA) ^ llo) << 4);
            const uint32_t offB = (uint32_t)(((2 * s + lk8B) ^ llo) << 4);
            uint32_t b[2][4];
#pragma unroll
            for (int p = 0; p < 2; p++)
                ldsm_x4(st + 2 * A_BYTES + bRow[p] + offB, b[p]);

            uint32_t ah[4][4];
#pragma unroll
            for (int i = 0; i < 4; i++) ldsm_x4(st + aRow[i] + offA, ah[i]);
#pragma unroll
            for (int i = 0; i < 4; i++)
#pragma unroll
                for (int j = 0; j < 4; j++)
                    mma16816(acc[i][j], ah[i], b[j >> 1][(j & 1) * 2 + 0],
                                               b[j >> 1][(j & 1) * 2 + 1]);

            uint32_t al[4][4];
#pragma unroll
            for (int i = 0; i < 4; i++)
                ldsm_x4(st + A_BYTES + aRow[i] + offA, al[i]);
#pragma unroll
            for (int i = 0; i < 4; i++)
#pragma unroll
                for (int j = 0; j < 4; j++)
                    mma16816(acc[i][j], al[i], b[j >> 1][(j & 1) * 2 + 0],
                                               b[j >> 1][(j & 1) * 2 + 1]);
        }
        __syncthreads();
        if (t + 2 < NKT) issue(t + 2);
    }

    const int g  = lid >> 2;
    const int t2 = (lid & 3) * 2;
#pragma unroll
    for (int i = 0; i < 4; i++) {
        const int row = bm + wm * 64 + i * 16 + g;
#pragma unroll
        for (int j = 0; j < 4; j++) {
            const int col = bn + wn * 32 + j * 8 + t2;
            if (Cf) {
                *(float2*)&Cf[(size_t)row * D_MODEL + col] =
                    make_float2(acc[i][j][0], acc[i][j][1]);
                *(float2*)&Cf[(size_t)(row + 8) * D_MODEL + col] =
                    make_float2(acc[i][j][2], acc[i][j][3]);
            } else if (Cl) {    // split output (Q)
                uint32_t h, l;
                packsplit(acc[i][j][0] * scl, acc[i][j][1] * scl, h, l);
                *(uint32_t*)&Ch[(size_t)row * D_MODEL + col] = h;
                *(uint32_t*)&Cl[(size_t)row * D_MODEL + col] = l;
                packsplit(acc[i][j][2] * scl, acc[i][j][3] * scl, h, l);
                *(uint32_t*)&Ch[(size_t)(row + 8) * D_MODEL + col] = h;
                *(uint32_t*)&Cl[(size_t)(row + 8) * D_MODEL + col] = l;
            } else {            // high-only output (K, V)
                *(uint32_t*)&Ch[(size_t)row * D_MODEL + col] =
                    packhi(acc[i][j][0], acc[i][j][1]);
                *(uint32_t*)&Ch[(size_t)(row + 8) * D_MODEL + col] =
                    packhi(acc[i][j][2], acc[i][j][3]);
            }
        }
    }
}

__global__ void __launch_bounds__(256, 2)
gemm_qkv() {
    const int z = blockIdx.z;
    if (z == 0)
        gemm_core(g_WH, nullptr, g_QH, g_QL, 0.125f);   // Q split, pre-scaled
    else if (z == 1)
        gemm_core(g_WH + DD, nullptr, g_KH, nullptr, 1.f);
    else
        gemm_core(g_WH + 2ull * DD, nullptr, g_VH, nullptr, 1.f);
}
__global__ void __launch_bounds__(256, 2)
gemm_o(float* __restrict__ out) {
    gemm_core(g_WH + 3ull * DD, out, nullptr, nullptr, 1.f);
}

// ---------------------------------------------------------------------------
// Tensor-core causal flash attention, fp16 2-term (R10, proven).
// S = (Qh+Ql)·Kh ; O += (Ph+Pl)·Vh. 3-stage KV pipeline; LPT block order.
// ---------------------------------------------------------------------------
#define AST 16640
#define SM_ATTN (3 * AST)    // 49920

__global__ void __launch_bounds__(128, 3)
attn_mma(const int* __restrict__ mask)
{
    extern __shared__ char smem[];
    const uint32_t sb = smem_u32(smem);
    const int tid = threadIdx.x, wid = tid >> 5, lid = tid & 31;
    const int qt = gridDim.x - 1 - blockIdx.x;      // LPT: heavy blocks first
    const int h = blockIdx.y, b = blockIdx.z;
    const int bm = qt * 64;
    const int nt = qt + 1;                // causal: key tiles 0..qt

    // ---- stage Q (QH|QL) into the stage area, extract fragments ----
    {
#pragma unroll
        for (int u = 0; u < 8; u++) {
            const int i = tid + u * 128;          // 0..1023
            const int arr = i >> 9;               // 0 QH, 1 QL
            const int j = i & 511;
            const int r = j >> 3, c = j & 7;
            const __half* src = (arr ? g_QL : g_QH) +
                (size_t)(b * SEQ + bm + r) * D_MODEL + h * HEAD_DIM + c * 8;
            cp_async16(sb + (uint32_t)arr * 8192 +
                       (uint32_t)r * 128 + (uint32_t)((c ^ (r & 7)) << 4), src);
        }
        cp_commit();
        cp_wait<0>();
        __syncthreads();
    }
    uint32_t aQh[4][4], aQl[4][4];
#pragma unroll
    for (int ks = 0; ks < 4; ks++) {
        const uint32_t off = (uint32_t)(wid * 16 + (lid & 15)) * 128 +
                             (uint32_t)(((2 * ks + (lid >> 4)) ^ (lid & 7)) << 4);
        ldsm_x4(sb + off, aQh[ks]);
        ldsm_x4(sb + 8192 + off, aQl[ks]);
    }
    __syncthreads();          // Q extracted; area reused for KV stages

    auto issueKV = [&](int ti) {
        const uint32_t st = sb + (uint32_t)(ti % 3) * AST;
        const int t0 = ti * 64;
#pragma unroll
        for (int u = 0; u < 8; u++) {
            const int i = tid + u * 128;          // 0..1023
            const int arr = i >> 9;               // 0 Kh, 1 Vh
            const int j = i & 511;
            const int r = j >> 3, c = j & 7;
            const __half* base = arr ? g_VH : g_KH;
            const __half* src = base +
                (size_t)(b * SEQ + t0 + r) * D_MODEL + h * HEAD_DIM + c * 8;
            cp_async16(st + (uint32_t)arr * 8192 +
                       (uint32_t)r * 128 + (uint32_t)((c ^ (r & 7)) << 4), src);
        }
        if (tid < 16)
            cp_async16(st + 16384 + tid * 16, mask + b * SEQ + t0 + tid * 4);
        cp_commit();
    };

    issueKV(0);
    if (nt > 1) issueKV(1);
    if (nt > 2) issueKV(2);

    float oreg[8][4];
#pragma unroll
    for (int j = 0; j < 8; j++)
#pragma unroll
        for (int q = 0; q < 4; q++) oreg[j][q] = 0.f;
    float mA = -1e30f, mB = -1e30f, lA = 0.f, lB = 0.f;
    const int q0 = bm + wid * 16 + (lid >> 2);

#pragma unroll 1
    for (int ti = 0; ti < nt; ti++) {
        const int rem = nt - ti;
        if (rem > 2)      cp_wait<2>();
        else if (rem == 2) cp_wait<1>();
        else               cp_wait<0>();
        __syncthreads();
        const uint32_t st = sb + (uint32_t)(ti % 3) * AST;
        const int* msk_s = (const int*)(smem + (ti % 3) * AST + 16384);
        const int t0 = ti * 64;

        // ---- S = (Qh + Ql) @ Kh^T ----
        float sr[8][4];
#pragma unroll
        for (int j = 0; j < 8; j++)
#pragma unroll
            for (int q = 0; q < 4; q++) sr[j][q] = 0.f;
#pragma unroll
        for (int ks = 0; ks < 4; ks++) {
            uint32_t bh[4][4];
#pragma unroll
            for (int nb = 0; nb < 4; nb++) {
                const uint32_t row = (uint32_t)(nb * 16 + (lid & 7) + ((lid >> 4) & 1) * 8);
                const uint32_t off = row * 128 +
                    (uint32_t)(((2 * ks + ((lid >> 3) & 1)) ^ (lid & 7)) << 4);
                ldsm_x4(st + off, bh[nb]);
            }
#pragma unroll
            for (int j = 0; j < 8; j++) {
                const uint32_t b0 = bh[j >> 1][(j & 1) * 2], b1 = bh[j >> 1][(j & 1) * 2 + 1];
                mma16816(sr[j], aQh[ks], b0, b1);
                mma16816(sr[j], aQl[ks], b0, b1);
            }
        }

        // ---- mask + online softmax ----
        const bool diag = (ti == qt);
#pragma unroll
        for (int j = 0; j < 8; j++) {
            const int c = j * 8 + (lid & 3) * 2;
            const int kg = t0 + c;
            const int mk0 = msk_s[c], mk1 = msk_s[c + 1];
            if (!mk0) { sr[j][0] = -1e30f; sr[j][2] = -1e30f; }
            if (!mk1) { sr[j][1] = -1e30f; sr[j][3] = -1e30f; }
            if (diag) {
                if (kg     > q0)     sr[j][0] = -1e30f;
                if (kg + 1 > q0)     sr[j][1] = -1e30f;
                if (kg     > q0 + 8) sr[j][2] = -1e30f;
                if (kg + 1 > q0 + 8) sr[j][3] = -1e30f;
            }
        }
        float tmA = -1e30f, tmB = -1e30f;
#pragma unroll
        for (int j = 0; j < 8; j++) {
            tmA = fmaxf(tmA, fmaxf(sr[j][0], sr[j][1]));
            tmB = fmaxf(tmB, fmaxf(sr[j][2], sr[j][3]));
        }
        tmA = fmaxf(tmA, __shfl_xor_sync(0xffffffff, tmA, 1));
        tmA = fmaxf(tmA, __shfl_xor_sync(0xffffffff, tmA, 2));
        tmB = fmaxf(tmB, __shfl_xor_sync(0xffffffff, tmB, 1));
        tmB = fmaxf(tmB, __shfl_xor_sync(0xffffffff, tmB, 2));
        const float nmA = fmaxf(mA, tmA), nmB = fmaxf(mB, tmB);
        const float corrA = __expf(mA - nmA), corrB = __expf(mB - nmB);
        mA = nmA; mB = nmB;
        float sA = 0.f, sB = 0.f;
#pragma unroll
        for (int j = 0; j < 8; j++) {
            sr[j][0] = __expf(sr[j][0] - nmA);
            sr[j][1] = __expf(sr[j][1] - nmA);
            sr[j][2] = __expf(sr[j][2] - nmB);
            sr[j][3] = __expf(sr[j][3] - nmB);
            sA += sr[j][0] + sr[j][1];
            sB += sr[j][2] + sr[j][3];
        }
        sA += __shfl_xor_sync(0xffffffff, sA, 1);
        sA += __shfl_xor_sync(0xffffffff, sA, 2);
        sB += __shfl_xor_sync(0xffffffff, sB, 1);
        sB += __shfl_xor_sync(0xffffffff, sB, 2);
        lA = lA * corrA + sA;
        lB = lB * corrB + sB;
#pragma unroll
        for (int j = 0; j < 8; j++) {
            oreg[j][0] *= corrA; oreg[j][1] *= corrA;
            oreg[j][2] *= corrB; oreg[j][3] *= corrB;
        }

        // ---- O += (Ph + Pl) @ Vh ----
#pragma unroll
        for (int ks = 0; ks < 4; ks++) {
            uint32_t aph[4], apl[4];
            packsplit(sr[2*ks][0],   sr[2*ks][1],   aph[0], apl[0]);
            packsplit(sr[2*ks][2],   sr[2*ks][3],   aph[1], apl[1]);
            packsplit(sr[2*ks+1][0], sr[2*ks+1][1], aph[2], apl[2]);
            packsplit(sr[2*ks+1][2], sr[2*ks+1][3], aph[3], apl[3]);
            uint32_t vh[4][4];
#pragma unroll
            for (int nb = 0; nb < 4; nb++) {
                const uint32_t row = (uint32_t)(ks * 16 + (lid & 7) + ((lid >> 3) & 1) * 8);
                const uint32_t chk = (uint32_t)(nb * 2 + (lid >> 4));
                const uint32_t off = row * 128 + ((chk ^ (lid & 7)) << 4);
                ldsm_x4t(st + 8192 + off, vh[nb]);
            }
#pragma unroll
            for (int j = 0; j < 8; j++) {
                const uint32_t b0 = vh[j >> 1][(j & 1) * 2], b1 = vh[j >> 1][(j & 1) * 2 + 1];
                mma16816(oreg[j], aph, b0, b1);
                mma16816(oreg[j], apl, b0, b1);
            }
        }

        __syncthreads();
        if (ti + 3 < nt) issueKV(ti + 3);
    }

    // ---- epilogue: normalize, split to fp16 h/l for the O-GEMM ----
    const float invA = 1.f / lA, invB = 1.f / lB;
    const size_t rA = (size_t)(b * SEQ + q0) * D_MODEL + h * HEAD_DIM;
    const size_t rB = rA + 8ull * D_MODEL;
#pragma unroll
    for (int j = 0; j < 8; j++) {
        const int col = j * 8 + (lid & 3) * 2;
        uint32_t hh, ll;
        packsplit(oreg[j][0] * invA, oreg[j][1] * invA, hh, ll);
        *(uint32_t*)&g_XH[rA + col] = hh;
        *(uint32_t*)&g_XL[rA + col] = ll;
        packsplit(oreg[j][2] * invB, oreg[j][3] * invB, hh, ll);
        *(uint32_t*)&g_XH[rB + col] = hh;
        *(uint32_t*)&g_XL[rB + col] = ll;
    }
}

// ---------------------------------------------------------------------------
// Launch. Inputs: x, attention_mask, wq, wk, wv, wo. Output fp32.
// ---------------------------------------------------------------------------
extern "C" void kernel_launch(void* const* d_in, const int* in_sizes, int n_in,
                              void* d_out, int out_size)
{
    const float* x    = (const float*)d_in[0];
    const int*   amsk = (const int*)  d_in[1];
    const float* wq   = (const float*)d_in[2];
    const float* wk   = (const float*)d_in[3];
    const float* wv   = (const float*)d_in[4];
    const float* wo   = (const float*)d_in[5];
    float*       out  = (float*)d_out;

    cudaFuncSetAttribute(gemm_qkv, cudaFuncAttributeMaxDynamicSharedMemorySize, SM_GEMM);
    cudaFuncSetAttribute(gemm_o,   cudaFuncAttributeMaxDynamicSharedMemorySize, SM_GEMM);
    cudaFuncSetAttribute(attn_mma, cudaFuncAttributeMaxDynamicSharedMemorySize, SM_ATTN);

    conv_all<<<dim3(2048, 1, 6), 256>>>(x, wq, wk, wv, wo);

    dim3 gQKV(D_MODEL / 128, M_ROWS / 128, 3);   // (8, 64, 3)
    gemm_qkv<<<gQKV, 256, SM_GEMM>>>();

    dim3 gAttn(SEQ / 64, N_HEADS, BATCH);        // (32, 16, 4)
    attn_mma<<<gAttn, 128, SM_ATTN>>>(amsk);

    dim3 gOut(D_MODEL / 128, M_ROWS / 128, 1);
    gemm_o<<<gOut, 256, SM_GEMM>>>(out);
}

// round 13
// speedup vs baseline: 2.5058x; 1.0845x over previous
#include <cuda_runtime.h>
#include <cuda_fp16.h>
#include <cstdint>
#include <math.h>

#define D_MODEL  1024
#define N_HEADS  16
#define HEAD_DIM 64
#define BATCH    4
#define SEQ      2048
#define M_ROWS   (BATCH * SEQ)   // 8192
#define DD       (D_MODEL * D_MODEL)

// ---------------------------------------------------------------------------
// Static scratch. fp16 2-term splits: only Q and X/AO need low parts.
// ---------------------------------------------------------------------------
__device__ __half g_QH[M_ROWS * D_MODEL];
__device__ __half g_QL[M_ROWS * D_MODEL];
__device__ __half g_KH[M_ROWS * D_MODEL];
__device__ __half g_VH[M_ROWS * D_MODEL];
__device__ __half g_XH[M_ROWS * D_MODEL];   // x, then attn-out (hi)
__device__ __half g_XL[M_ROWS * D_MODEL];   // x, then attn-out (lo)
__device__ __half g_WH[4 * DD];             // wq,wk,wv,wo hi
__device__ __half g_WL[4 * DD];             // wq,wk,wv,wo lo

// ---------------------------------------------------------------------------
// Helpers (compute_103-safe)
// ---------------------------------------------------------------------------
__device__ __forceinline__ uint32_t smem_u32(const void* p) {
    uint32_t a;
    asm("{ .reg .u64 t; cvta.to.shared.u64 t, %1; cvt.u32.u64 %0, t; }"
        : "=r"(a) : "l"(p));
    return a;
}
__device__ __forceinline__ float ex2f(float x) {
    float r;
    asm("ex2.approx.f32 %0, %1;" : "=f"(r) : "f"(x));
    return r;
}
__device__ __forceinline__ void cp_async16(uint32_t dst, const void* src) {
    asm volatile("cp.async.cg.shared.global [%0], [%1], 16;\n"
                 :: "r"(dst), "l"(src) : "memory");
}
__device__ __forceinline__ void cp_commit() {
    asm volatile("cp.async.commit_group;\n" ::: "memory");
}
template <int N>
__device__ __forceinline__ void cp_wait() {
    asm volatile("cp.async.wait_group %0;\n" :: "n"(N) : "memory");
}
__device__ __forceinline__ void ldsm_x4(uint32_t addr, uint32_t* r) {
    asm volatile("ldmatrix.sync.aligned.m8n8.x4.shared.b16 {%0,%1,%2,%3}, [%4];\n"
                 : "=r"(r[0]), "=r"(r[1]), "=r"(r[2]), "=r"(r[3]) : "r"(addr));
}
__device__ __forceinline__ void ldsm_x4t(uint32_t addr, uint32_t* r) {
    asm volatile("ldmatrix.sync.aligned.m8n8.x4.trans.shared.b16 {%0,%1,%2,%3}, [%4];\n"
                 : "=r"(r[0]), "=r"(r[1]), "=r"(r[2]), "=r"(r[3]) : "r"(addr));
}
__device__ __forceinline__ void mma16816(float* c, const uint32_t* a,
                                         uint32_t b0, uint32_t b1) {
    asm volatile(
        "mma.sync.aligned.m16n8k16.row.col.f32.f16.f16.f32 "
        "{%0,%1,%2,%3}, {%4,%5,%6,%7}, {%8,%9}, {%0,%1,%2,%3};\n"
        : "+f"(c[0]), "+f"(c[1]), "+f"(c[2]), "+f"(c[3])
        : "r"(a[0]), "r"(a[1]), "r"(a[2]), "r"(a[3]), "r"(b0), "r"(b1));
}
__device__ __forceinline__ void packsplit(float x, float y,
                                          uint32_t& hi, uint32_t& lo) {
    __half2 H = __floats2half2_rn(x, y);
    float2 Hf = __half22float2(H);
    __half2 L = __floats2half2_rn(x - Hf.x, y - Hf.y);
    hi = *(uint32_t*)&H;
    lo = *(uint32_t*)&L;
}
__device__ __forceinline__ uint32_t packhi(float x, float y) {
    __half2 H = __floats2half2_rn(x, y);
    return *(uint32_t*)&H;
}

// ---------------------------------------------------------------------------
// Merged split conversion: z 0..3 -> quarters of x, z=4 -> wq|wk, z=5 -> wv|wo
// ---------------------------------------------------------------------------
__device__ __forceinline__ void split4(float4 v, __half* h, __half* l,
                                       size_t idx4) {
    uint32_t h0, l0, h1, l1;
    packsplit(v.x, v.y, h0, l0);
    packsplit(v.z, v.w, h1, l1);
    ((uint32_t*)h)[idx4 * 2 + 0] = h0;
    ((uint32_t*)h)[idx4 * 2 + 1] = h1;
    ((uint32_t*)l)[idx4 * 2 + 0] = l0;
    ((uint32_t*)l)[idx4 * 2 + 1] = l1;
}
__global__ void conv_all(const float* __restrict__ x,
                         const float* __restrict__ w0, const float* __restrict__ w1,
                         const float* __restrict__ w2, const float* __restrict__ w3)
{
    const int z = blockIdx.z;
    const size_t bx = blockIdx.x;                      // 0..2047
    const size_t li = bx * blockDim.x + threadIdx.x;   // 0..524287 (float4 idx)
    if (z < 4) {
        const size_t i = (size_t)z * 524288 + li;      // x: 2M float4 total
        split4(((const float4*)x)[i], g_XH, g_XL, i);
    } else {
        const int wsel = (z - 4) * 2 + (int)(li >> 18);    // 0..3
        const size_t i = li & 262143;                      // DD/4 = 262144
        const float* w = (wsel == 0) ? w0 : (wsel == 1) ? w1
                       : (wsel == 2) ? w2 : w3;
        split4(((const float4*)w)[i], g_WH + (size_t)wsel * DD,
               g_WL + (size_t)wsel * DD, i);
    }
}

// ---------------------------------------------------------------------------
// Fused 2-term split-fp16 GEMM (R11, proven): per k-tile stage Ah|Al|B once.
// BK=64, 2-stage cp.async, 16 iterations. Stage 48KB; 2 CTAs/SM.
// ---------------------------------------------------------------------------
#define BK      64
#define NKT     (D_MODEL / BK)    // 16
#define A_BYTES (128 * 128)       // 16384
#define STAGE   (3 * A_BYTES)     // 49152
#define SM_GEMM (2 * STAGE)       // 98304

__device__ __forceinline__ void gemm_core(const __half* __restrict__ Bh,
                                          float* __restrict__ Cf,
                                          __half* __restrict__ Ch,
                                          __half* __restrict__ Cl,
                                          float scl)
{
    extern __shared__ char smem[];
    const uint32_t sb = smem_u32(smem);
    const int tid = threadIdx.x;
    const int wid = tid >> 5, lid = tid & 31;
    const int wm  = wid >> 2, wn = wid & 3;
    const int bm  = blockIdx.y * 128, bn = blockIdx.x * 128;

    const int llo  = lid & 7;
    const int lr15 = lid & 15;
    const int lhiA = lid >> 4;
    const int lk8B = (lid >> 3) & 1;
    uint32_t aRow[4], bRow[2];
#pragma unroll
    for (int i = 0; i < 4; i++) aRow[i] = (uint32_t)(wm * 64 + i * 16 + lr15) * 128;
#pragma unroll
    for (int p = 0; p < 2; p++)
        bRow[p] = (uint32_t)(wn * 32 + p * 16 + llo + ((lid >> 4) & 1) * 8) * 128;

    float acc[4][4][4];
#pragma unroll
    for (int i = 0; i < 4; i++)
#pragma unroll
        for (int j = 0; j < 4; j++)
#pragma unroll
            for (int q = 0; q < 4; q++) acc[i][j][q] = 0.f;

    auto issue = [&](int kt) {
        const uint32_t st = sb + (uint32_t)(kt & 1) * STAGE;
        const int k0 = kt * BK;
#pragma unroll
        for (int u = 0; u < 12; u++) {
            const int i = tid + u * 256;              // 0..3071
            const int arr = i >> 10;                  // 0 Ah, 1 Al, 2 B
            const int j = i & 1023;
            const int r = j >> 3, c = j & 7;
            const __half* src =
                (arr == 0) ? g_XH + (size_t)(bm + r) * D_MODEL + k0 + c * 8
              : (arr == 1) ? g_XL + (size_t)(bm + r) * D_MODEL + k0 + c * 8
                           : Bh   + (size_t)(bn + r) * D_MODEL + k0 + c * 8;
            const uint32_t dst = st + (uint32_t)arr * A_BYTES +
                                 (uint32_t)r * 128 + (uint32_t)((c ^ (r & 7)) << 4);
            cp_async16(dst, src);
        }
        cp_commit();
    };

    issue(0);
    issue(1);

#pragma unroll 1
    for (int t = 0; t < NKT; t++) {
        if (t == NKT - 1) cp_wait<0>(); else cp_wait<1>();
        __syncthreads();

        const uint32_t st = sb + (uint32_t)(t & 1) * STAGE;
#pragma unroll
        for (int s = 0; s < 4; s++) {
            const uint32_t offA = (uint32_t)(((2 * s + lhiA) ^ llo) << 4);
            const uint32_t offB = (uint32_t)(((2 * s + lk8B) ^ llo) << 4);
            uint32_t b[2][4];
#pragma unroll
            for (int p = 0; p < 2; p++)
                ldsm_x4(st + 2 * A_BYTES + bRow[p] + offB, b[p]);

            uint32_t ah[4][4];
#pragma unroll
            for (int i = 0; i < 4; i++) ldsm_x4(st + aRow[i] + offA, ah[i]);
#pragma unroll
            for (int i = 0; i < 4; i++)
#pragma unroll
                for (int j = 0; j < 4; j++)
                    mma16816(acc[i][j], ah[i], b[j >> 1][(j & 1) * 2 + 0],
                                               b[j >> 1][(j & 1) * 2 + 1]);

            uint32_t al[4][4];
#pragma unroll
            for (int i = 0; i < 4; i++)
                ldsm_x4(st + A_BYTES + aRow[i] + offA, al[i]);
#pragma unroll
            for (int i = 0; i < 4; i++)
#pragma unroll
                for (int j = 0; j < 4; j++)
                    mma16816(acc[i][j], al[i], b[j >> 1][(j & 1) * 2 + 0],
                                               b[j >> 1][(j & 1) * 2 + 1]);
        }
        __syncthreads();
        if (t + 2 < NKT) issue(t + 2);
    }

    const int g  = lid >> 2;
    const int t2 = (lid & 3) * 2;
#pragma unroll
    for (int i = 0; i < 4; i++) {
        const int row = bm + wm * 64 + i * 16 + g;
#pragma unroll
        for (int j = 0; j < 4; j++) {
            const int col = bn + wn * 32 + j * 8 + t2;
            if (Cf) {
                *(float2*)&Cf[(size_t)row * D_MODEL + col] =
                    make_float2(acc[i][j][0], acc[i][j][1]);
                *(float2*)&Cf[(size_t)(row + 8) * D_MODEL + col] =
                    make_float2(acc[i][j][2], acc[i][j][3]);
            } else if (Cl) {    // split output (Q)
                uint32_t h, l;
                packsplit(acc[i][j][0] * scl, acc[i][j][1] * scl, h, l);
                *(uint32_t*)&Ch[(size_t)row * D_MODEL + col] = h;
                *(uint32_t*)&Cl[(size_t)row * D_MODEL + col] = l;
                packsplit(acc[i][j][2] * scl, acc[i][j][3] * scl, h, l);
                *(uint32_t*)&Ch[(size_t)(row + 8) * D_MODEL + col] = h;
                *(uint32_t*)&Cl[(size_t)(row + 8) * D_MODEL + col] = l;
            } else {            // high-only output (K, V)
                *(uint32_t*)&Ch[(size_t)row * D_MODEL + col] =
                    packhi(acc[i][j][0], acc[i][j][1]);
                *(uint32_t*)&Ch[(size_t)(row + 8) * D_MODEL + col] =
                    packhi(acc[i][j][2], acc[i][j][3]);
            }
        }
    }
}

// Q pre-scale folds softmax scale AND log2(e) so attention can use exp2:
// S_log2 = (q . k) * 0.125 * log2(e)
#define QSCALE 0.18033688011112042f   // 0.125 * 1.4426950408889634

__global__ void __launch_bounds__(256, 2)
gemm_qkv() {
    const int z = blockIdx.z;
    if (z == 0)
        gemm_core(g_WH, nullptr, g_QH, g_QL, QSCALE);
    else if (z == 1)
        gemm_core(g_WH + DD, nullptr, g_KH, nullptr, 1.f);
    else
        gemm_core(g_WH + 2ull * DD, nullptr, g_VH, nullptr, 1.f);
}
__global__ void __launch_bounds__(256, 2)
gemm_o(float* __restrict__ out) {
    gemm_core(g_WH + 3ull * DD, out, nullptr, nullptr, 1.f);
}

// ---------------------------------------------------------------------------
// Tensor-core causal flash attention. S = (Qh+Ql)·Kh (2 terms, abs-accuracy
// critical); O += Ph·Vh (1 term — P in [0,1] enters linearly, fp16 rounding
// adds only ~2.5e-4). Softmax in log2 domain (ex2.approx). 3-stage KV pipe.
// ---------------------------------------------------------------------------
#define AST 16640
#define SM_ATTN (3 * AST)    // 49920

__global__ void __launch_bounds__(128, 3)
attn_mma(const int* __restrict__ mask)
{
    extern __shared__ char smem[];
    const uint32_t sb = smem_u32(smem);
    const int tid = threadIdx.x, wid = tid >> 5, lid = tid & 31;
    const int qt = gridDim.x - 1 - blockIdx.x;      // LPT: heavy blocks first
    const int h = blockIdx.y, b = blockIdx.z;
    const int bm = qt * 64;
    const int nt = qt + 1;                // causal: key tiles 0..qt

    // ---- stage Q (QH|QL) into the stage area, extract fragments ----
    {
#pragma unroll
        for (int u = 0; u < 8; u++) {
            const int i = tid + u * 128;          // 0..1023
            const int arr = i >> 9;               // 0 QH, 1 QL
            const int j = i & 511;
            const int r = j >> 3, c = j & 7;
            const __half* src = (arr ? g_QL : g_QH) +
                (size_t)(b * SEQ + bm + r) * D_MODEL + h * HEAD_DIM + c * 8;
            cp_async16(sb + (uint32_t)arr * 8192 +
                       (uint32_t)r * 128 + (uint32_t)((c ^ (r & 7)) << 4), src);
        }
        cp_commit();
        cp_wait<0>();
        __syncthreads();
    }
    uint32_t aQh[4][4], aQl[4][4];
#pragma unroll
    for (int ks = 0; ks < 4; ks++) {
        const uint32_t off = (uint32_t)(wid * 16 + (lid & 15)) * 128 +
                             (uint32_t)(((2 * ks + (lid >> 4)) ^ (lid & 7)) << 4);
        ldsm_x4(sb + off, aQh[ks]);
        ldsm_x4(sb + 8192 + off, aQl[ks]);
    }
    __syncthreads();          // Q extracted; area reused for KV stages

    auto issueKV = [&](int ti) {
        const uint32_t st = sb + (uint32_t)(ti % 3) * AST;
        const int t0 = ti * 64;
#pragma unroll
        for (int u = 0; u < 8; u++) {
            const int i = tid + u * 128;          // 0..1023
            const int arr = i >> 9;               // 0 Kh, 1 Vh
            const int j = i & 511;
            const int r = j >> 3, c = j & 7;
            const __half* base = arr ? g_VH : g_KH;
            const __half* src = base +
                (size_t)(b * SEQ + t0 + r) * D_MODEL + h * HEAD_DIM + c * 8;
            cp_async16(st + (uint32_t)arr * 8192 +
                       (uint32_t)r * 128 + (uint32_t)((c ^ (r & 7)) << 4), src);
        }
        if (tid < 16)
            cp_async16(st + 16384 + tid * 16, mask + b * SEQ + t0 + tid * 4);
        cp_commit();
    };

    issueKV(0);
    if (nt > 1) issueKV(1);
    if (nt > 2) issueKV(2);

    float oreg[8][4];
#pragma unroll
    for (int j = 0; j < 8; j++)
#pragma unroll
        for (int q = 0; q < 4; q++) oreg[j][q] = 0.f;
    float mA = -1e30f, mB = -1e30f, lA = 0.f, lB = 0.f;
    const int q0 = bm + wid * 16 + (lid >> 2);

#pragma unroll 1
    for (int ti = 0; ti < nt; ti++) {
        const int rem = nt - ti;
        if (rem > 2)      cp_wait<2>();
        else if (rem == 2) cp_wait<1>();
        else               cp_wait<0>();
        __syncthreads();
        const uint32_t st = sb + (uint32_t)(ti % 3) * AST;
        const int* msk_s = (const int*)(smem + (ti % 3) * AST + 16384);
        const int t0 = ti * 64;

        // ---- S(log2) = (Qh + Ql) @ Kh^T ----
        float sr[8][4];
#pragma unroll
        for (int j = 0; j < 8; j++)
#pragma unroll
            for (int q = 0; q < 4; q++) sr[j][q] = 0.f;
#pragma unroll
        for (int ks = 0; ks < 4; ks++) {
            uint32_t bh[4][4];
#pragma unroll
            for (int nb = 0; nb < 4; nb++) {
                const uint32_t row = (uint32_t)(nb * 16 + (lid & 7) + ((lid >> 4) & 1) * 8);
                const uint32_t off = row * 128 +
                    (uint32_t)(((2 * ks + ((lid >> 3) & 1)) ^ (lid & 7)) << 4);
                ldsm_x4(st + off, bh[nb]);
            }
#pragma unroll
            for (int j = 0; j < 8; j++) {
                const uint32_t b0 = bh[j >> 1][(j & 1) * 2], b1 = bh[j >> 1][(j & 1) * 2 + 1];
                mma16816(sr[j], aQh[ks], b0, b1);
                mma16816(sr[j], aQl[ks], b0, b1);
            }
        }

        // ---- mask + online softmax (log2 domain) ----
        const bool diag = (ti == qt);
#pragma unroll
        for (int j = 0; j < 8; j++) {
            const int c = j * 8 + (lid & 3) * 2;
            const int kg = t0 + c;
            const int mk0 = msk_s[c], mk1 = msk_s[c + 1];
            if (!mk0) { sr[j][0] = -1e30f; sr[j][2] = -1e30f; }
            if (!mk1) { sr[j][1] = -1e30f; sr[j][3] = -1e30f; }
            if (diag) {
                if (kg     > q0)     sr[j][0] = -1e30f;
                if (kg + 1 > q0)     sr[j][1] = -1e30f;
                if (kg     > q0 + 8) sr[j][2] = -1e30f;
                if (kg + 1 > q0 + 8) sr[j][3] = -1e30f;
            }
        }
        float tmA = -1e30f, tmB = -1e30f;
#pragma unroll
        for (int j = 0; j < 8; j++) {
            tmA = fmaxf(tmA, fmaxf(sr[j][0], sr[j][1]));
            tmB = fmaxf(tmB, fmaxf(sr[j][2], sr[j][3]));
        }
        tmA = fmaxf(tmA, __shfl_xor_sync(0xffffffff, tmA, 1));
        tmA = fmaxf(tmA, __shfl_xor_sync(0xffffffff, tmA, 2));
        tmB = fmaxf(tmB, __shfl_xor_sync(0xffffffff, tmB, 1));
        tmB = fmaxf(tmB, __shfl_xor_sync(0xffffffff, tmB, 2));
        const float nmA = fmaxf(mA, tmA), nmB = fmaxf(mB, tmB);
        const float corrA = ex2f(mA - nmA), corrB = ex2f(mB - nmB);
        mA = nmA; mB = nmB;
        float sA = 0.f, sB = 0.f;
#pragma unroll
        for (int j = 0; j < 8; j++) {
            sr[j][0] = ex2f(sr[j][0] - nmA);
            sr[j][1] = ex2f(sr[j][1] - nmA);
            sr[j][2] = ex2f(sr[j][2] - nmB);
            sr[j][3] = ex2f(sr[j][3] - nmB);
            sA += sr[j][0] + sr[j][1];
            sB += sr[j][2] + sr[j][3];
        }
        sA += __shfl_xor_sync(0xffffffff, sA, 1);
        sA += __shfl_xor_sync(0xffffffff, sA, 2);
        sB += __shfl_xor_sync(0xffffffff, sB, 1);
        sB += __shfl_xor_sync(0xffffffff, sB, 2);
        lA = lA * corrA + sA;
        lB = lB * corrB + sB;
#pragma unroll
        for (int j = 0; j < 8; j++) {
            oreg[j][0] *= corrA; oreg[j][1] *= corrA;
            oreg[j][2] *= corrB; oreg[j][3] *= corrB;
        }

        // ---- O += Ph @ Vh (single term) ----
#pragma unroll
        for (int ks = 0; ks < 4; ks++) {
            uint32_t aph[4];
            aph[0] = packhi(sr[2*ks][0],   sr[2*ks][1]);
            aph[1] = packhi(sr[2*ks][2],   sr[2*ks][3]);
            aph[2] = packhi(sr[2*ks+1][0], sr[2*ks+1][1]);
            aph[3] = packhi(sr[2*ks+1][2], sr[2*ks+1][3]);
            uint32_t vh[4][4];
#pragma unroll
            for (int nb = 0; nb < 4; nb++) {
                const uint32_t row = (uint32_t)(ks * 16 + (lid & 7) + ((lid >> 3) & 1) * 8);
                const uint32_t chk = (uint32_t)(nb * 2 + (lid >> 4));
                const uint32_t off = row * 128 + ((chk ^ (lid & 7)) << 4);
                ldsm_x4t(st + 8192 + off, vh[nb]);
            }
#pragma unroll
            for (int j = 0; j < 8; j++) {
                const uint32_t b0 = vh[j >> 1][(j & 1) * 2], b1 = vh[j >> 1][(j & 1) * 2 + 1];
                mma16816(oreg[j], aph, b0, b1);
            }
        }

        __syncthreads();
        if (ti + 3 < nt) issueKV(ti + 3);
    }

    // ---- epilogue: normalize, split to fp16 h/l for the O-GEMM ----
    const float invA = 1.f / lA, invB = 1.f / lB;
    const size_t rA = (size_t)(b * SEQ + q0) * D_MODEL + h * HEAD_DIM;
    const size_t rB = rA + 8ull * D_MODEL;
#pragma unroll
    for (int j = 0; j < 8; j++) {
        const int col = j * 8 + (lid & 3) * 2;
        uint32_t hh, ll;
        packsplit(oreg[j][0] * invA, oreg[j][1] * invA, hh, ll);
        *(uint32_t*)&g_XH[rA + col] = hh;
        *(uint32_t*)&g_XL[rA + col] = ll;
        packsplit(oreg[j][2] * invB, oreg[j][3] * invB, hh, ll);
        *(uint32_t*)&g_XH[rB + col] = hh;
        *(uint32_t*)&g_XL[rB + col] = ll;
    }
}

// ---------------------------------------------------------------------------
// Launch. Inputs: x, attention_mask, wq, wk, wv, wo. Output fp32.
// ---------------------------------------------------------------------------
extern "C" void kernel_launch(void* const* d_in, const int* in_sizes, int n_in,
                              void* d_out, int out_size)
{
    const float* x    = (const float*)d_in[0];
    const int*   amsk = (const int*)  d_in[1];
    const float* wq   = (const float*)d_in[2];
    const float* wk   = (const float*)d_in[3];
    const float* wv   = (const float*)d_in[4];
    const float* wo   = (const float*)d_in[5];
    float*       out  = (float*)d_out;

    cudaFuncSetAttribute(gemm_qkv, cudaFuncAttributeMaxDynamicSharedMemorySize, SM_GEMM);
    cudaFuncSetAttribute(gemm_o,   cudaFuncAttributeMaxDynamicSharedMemorySize, SM_GEMM);
    cudaFuncSetAttribute(attn_mma, cudaFuncAttributeMaxDynamicSharedMemorySize, SM_ATTN);

    conv_all<<<dim3(2048, 1, 6), 256>>>(x, wq, wk, wv, wo);

    dim3 gQKV(D_MODEL / 128, M_ROWS / 128, 3);   // (8, 64, 3)
    gemm_qkv<<<gQKV, 256, SM_GEMM>>>();

    dim3 gAttn(SEQ / 64, N_HEADS, BATCH);        // (32, 16, 4)
    attn_mma<<<gAttn, 128, SM_ATTN>>>(amsk);

    dim3 gOut(D_MODEL / 128, M_ROWS / 128, 1);
    gemm_o<<<gOut, 256, SM_GEMM>>>(out);
}

// round 14
// speedup vs baseline: 2.9229x; 1.1664x over previous
#include <cuda_runtime.h>
#include <cuda_fp16.h>
#include <cstdint>
#include <math.h>

#define D_MODEL  1024
#define N_HEADS  16
#define HEAD_DIM 64
#define BATCH    4
#define SEQ      2048
#define M_ROWS   (BATCH * SEQ)   // 8192
#define DD       (D_MODEL * D_MODEL)

// ---------------------------------------------------------------------------
// Static scratch. fp16 2-term splits: only Q and X/AO need low parts.
// ---------------------------------------------------------------------------
__device__ __half g_QH[M_ROWS * D_MODEL];
__device__ __half g_QL[M_ROWS * D_MODEL];
__device__ __half g_KH[M_ROWS * D_MODEL];
__device__ __half g_VH[M_ROWS * D_MODEL];
__device__ __half g_XH[M_ROWS * D_MODEL];   // x, then attn-out (hi)
__device__ __half g_XL[M_ROWS * D_MODEL];   // x, then attn-out (lo)
__device__ __half g_WH[4 * DD];             // wq,wk,wv,wo hi
__device__ __half g_WL[4 * DD];             // wq,wk,wv,wo lo

// ---------------------------------------------------------------------------
// Helpers (compute_103-safe)
// ---------------------------------------------------------------------------
__device__ __forceinline__ uint32_t smem_u32(const void* p) {
    uint32_t a;
    asm("{ .reg .u64 t; cvta.to.shared.u64 t, %1; cvt.u32.u64 %0, t; }"
        : "=r"(a) : "l"(p));
    return a;
}
__device__ __forceinline__ float ex2f(float x) {
    float r;
    asm("ex2.approx.f32 %0, %1;" : "=f"(r) : "f"(x));
    return r;
}
__device__ __forceinline__ void cp_async16(uint32_t dst, const void* src) {
    asm volatile("cp.async.cg.shared.global [%0], [%1], 16;\n"
                 :: "r"(dst), "l"(src) : "memory");
}
__device__ __forceinline__ void cp_commit() {
    asm volatile("cp.async.commit_group;\n" ::: "memory");
}
template <int N>
__device__ __forceinline__ void cp_wait() {
    asm volatile("cp.async.wait_group %0;\n" :: "n"(N) : "memory");
}
__device__ __forceinline__ void ldsm_x4(uint32_t addr, uint32_t* r) {
    asm volatile("ldmatrix.sync.aligned.m8n8.x4.shared.b16 {%0,%1,%2,%3}, [%4];\n"
                 : "=r"(r[0]), "=r"(r[1]), "=r"(r[2]), "=r"(r[3]) : "r"(addr));
}
__device__ __forceinline__ void ldsm_x4t(uint32_t addr, uint32_t* r) {
    asm volatile("ldmatrix.sync.aligned.m8n8.x4.trans.shared.b16 {%0,%1,%2,%3}, [%4];\n"
                 : "=r"(r[0]), "=r"(r[1]), "=r"(r[2]), "=r"(r[3]) : "r"(addr));
}
__device__ __forceinline__ void mma16816(float* c, const uint32_t* a,
                                         uint32_t b0, uint32_t b1) {
    asm volatile(
        "mma.sync.aligned.m16n8k16.row.col.f32.f16.f16.f32 "
        "{%0,%1,%2,%3}, {%4,%5,%6,%7}, {%8,%9}, {%0,%1,%2,%3};\n"
        : "+f"(c[0]), "+f"(c[1]), "+f"(c[2]), "+f"(c[3])
        : "r"(a[0]), "r"(a[1]), "r"(a[2]), "r"(a[3]), "r"(b0), "r"(b1));
}
__device__ __forceinline__ void packsplit(float x, float y,
                                          uint32_t& hi, uint32_t& lo) {
    __half2 H = __floats2half2_rn(x, y);
    float2 Hf = __half22float2(H);
    __half2 L = __floats2half2_rn(x - Hf.x, y - Hf.y);
    hi = *(uint32_t*)&H;
    lo = *(uint32_t*)&L;
}
__device__ __forceinline__ uint32_t packhi(float x, float y) {
    __half2 H = __floats2half2_rn(x, y);
    return *(uint32_t*)&H;
}

// ---------------------------------------------------------------------------
// Merged split conversion: z 0..3 -> quarters of x, z=4 -> wq|wk, z=5 -> wv|wo
// ---------------------------------------------------------------------------
__device__ __forceinline__ void split4(float4 v, __half* h, __half* l,
                                       size_t idx4) {
    uint32_t h0, l0, h1, l1;
    packsplit(v.x, v.y, h0, l0);
    packsplit(v.z, v.w, h1, l1);
    ((uint32_t*)h)[idx4 * 2 + 0] = h0;
    ((uint32_t*)h)[idx4 * 2 + 1] = h1;
    ((uint32_t*)l)[idx4 * 2 + 0] = l0;
    ((uint32_t*)l)[idx4 * 2 + 1] = l1;
}
__global__ void conv_all(const float* __restrict__ x,
                         const float* __restrict__ w0, const float* __restrict__ w1,
                         const float* __restrict__ w2, const float* __restrict__ w3)
{
    const int z = blockIdx.z;
    const size_t bx = blockIdx.x;                      // 0..2047
    const size_t li = bx * blockDim.x + threadIdx.x;   // 0..524287 (float4 idx)
    if (z < 4) {
        const size_t i = (size_t)z * 524288 + li;      // x: 2M float4 total
        split4(((const float4*)x)[i], g_XH, g_XL, i);
    } else {
        const int wsel = (z - 4) * 2 + (int)(li >> 18);    // 0..3
        const size_t i = li & 262143;                      // DD/4 = 262144
        const float* w = (wsel == 0) ? w0 : (wsel == 1) ? w1
                       : (wsel == 2) ? w2 : w3;
        split4(((const float4*)w)[i], g_WH + (size_t)wsel * DD,
               g_WL + (size_t)wsel * DD, i);
    }
}

// ---------------------------------------------------------------------------
// Split-fp16 GEMM, templated term count.
// TWO=true : C = Ah*Bh + Al*Bh (Q projection, output GEMM)
// TWO=false: C = Ah*Bh         (K, V projections — output rounded to fp16
//            anyway, so the Al correction is below the rounding floor)
// BK=64, 2-stage cp.async. Stage layout: Ah | (Al) | B at fixed offsets.
// ---------------------------------------------------------------------------
#define BK      64
#define NKT     (D_MODEL / BK)    // 16
#define A_BYTES (128 * 128)       // 16384
#define STAGE   (3 * A_BYTES)     // 49152
#define SM_GEMM (2 * STAGE)       // 98304

template <bool TWO>
__device__ __forceinline__ void gemm_core(const __half* __restrict__ Bh,
                                          float* __restrict__ Cf,
                                          __half* __restrict__ Ch,
                                          __half* __restrict__ Cl,
                                          float scl)
{
    extern __shared__ char smem[];
    const uint32_t sb = smem_u32(smem);
    const int tid = threadIdx.x;
    const int wid = tid >> 5, lid = tid & 31;
    const int wm  = wid >> 2, wn = wid & 3;
    const int bm  = blockIdx.y * 128, bn = blockIdx.x * 128;

    const int llo  = lid & 7;
    const int lr15 = lid & 15;
    const int lhiA = lid >> 4;
    const int lk8B = (lid >> 3) & 1;
    uint32_t aRow[4], bRow[2];
#pragma unroll
    for (int i = 0; i < 4; i++) aRow[i] = (uint32_t)(wm * 64 + i * 16 + lr15) * 128;
#pragma unroll
    for (int p = 0; p < 2; p++)
        bRow[p] = (uint32_t)(wn * 32 + p * 16 + llo + ((lid >> 4) & 1) * 8) * 128;

    float acc[4][4][4];
#pragma unroll
    for (int i = 0; i < 4; i++)
#pragma unroll
        for (int j = 0; j < 4; j++)
#pragma unroll
            for (int q = 0; q < 4; q++) acc[i][j][q] = 0.f;

    auto issue = [&](int kt) {
        const uint32_t st = sb + (uint32_t)(kt & 1) * STAGE;
        const int k0 = kt * BK;
        constexpr int NCH = TWO ? 12 : 8;       // 16B chunks per thread
#pragma unroll
        for (int u = 0; u < NCH; u++) {
            const int i = tid + u * 256;
            const int arr = i >> 10;            // TWO: 0 Ah,1 Al,2 B ; else 0 Ah,1 B
            const int j = i & 1023;
            const int r = j >> 3, c = j & 7;
            const __half* src;
            uint32_t dstArr;
            if (TWO) {
                src = (arr == 0) ? g_XH + (size_t)(bm + r) * D_MODEL + k0 + c * 8
                    : (arr == 1) ? g_XL + (size_t)(bm + r) * D_MODEL + k0 + c * 8
                                 : Bh   + (size_t)(bn + r) * D_MODEL + k0 + c * 8;
                dstArr = (uint32_t)arr;
            } else {
                src = (arr == 0) ? g_XH + (size_t)(bm + r) * D_MODEL + k0 + c * 8
                                 : Bh   + (size_t)(bn + r) * D_MODEL + k0 + c * 8;
                dstArr = (arr == 0) ? 0u : 2u;  // B stays at 2*A_BYTES
            }
            const uint32_t dst = st + dstArr * A_BYTES +
                                 (uint32_t)r * 128 + (uint32_t)((c ^ (r & 7)) << 4);
            cp_async16(dst, src);
        }
        cp_commit();
    };

    issue(0);
    issue(1);

#pragma unroll 1
    for (int t = 0; t < NKT; t++) {
        if (t == NKT - 1) cp_wait<0>(); else cp_wait<1>();
        __syncthreads();

        const uint32_t st = sb + (uint32_t)(t & 1) * STAGE;
#pragma unroll
        for (int s = 0; s < 4; s++) {
            const uint32_t offA = (uint32_t)(((2 * s + lhiA) ^ llo) << 4);
            const uint32_t offB = (uint32_t)(((2 * s + lk8B) ^ llo) << 4);
            uint32_t b[2][4];
#pragma unroll
            for (int p = 0; p < 2; p++)
                ldsm_x4(st + 2 * A_BYTES + bRow[p] + offB, b[p]);

            uint32_t ah[4][4];
#pragma unroll
            for (int i = 0; i < 4; i++) ldsm_x4(st + aRow[i] + offA, ah[i]);
#pragma unroll
            for (int i = 0; i < 4; i++)
#pragma unroll
                for (int j = 0; j < 4; j++)
                    mma16816(acc[i][j], ah[i], b[j >> 1][(j & 1) * 2 + 0],
                                               b[j >> 1][(j & 1) * 2 + 1]);

            if (TWO) {
                uint32_t al[4][4];
#pragma unroll
                for (int i = 0; i < 4; i++)
                    ldsm_x4(st + A_BYTES + aRow[i] + offA, al[i]);
#pragma unroll
                for (int i = 0; i < 4; i++)
#pragma unroll
                    for (int j = 0; j < 4; j++)
                        mma16816(acc[i][j], al[i], b[j >> 1][(j & 1) * 2 + 0],
                                                   b[j >> 1][(j & 1) * 2 + 1]);
            }
        }
        __syncthreads();
        if (t + 2 < NKT) issue(t + 2);
    }

    const int g  = lid >> 2;
    const int t2 = (lid & 3) * 2;
#pragma unroll
    for (int i = 0; i < 4; i++) {
        const int row = bm + wm * 64 + i * 16 + g;
#pragma unroll
        for (int j = 0; j < 4; j++) {
            const int col = bn + wn * 32 + j * 8 + t2;
            if (Cf) {
                *(float2*)&Cf[(size_t)row * D_MODEL + col] =
                    make_float2(acc[i][j][0], acc[i][j][1]);
                *(float2*)&Cf[(size_t)(row + 8) * D_MODEL + col] =
                    make_float2(acc[i][j][2], acc[i][j][3]);
            } else if (Cl) {    // split output (Q)
                uint32_t h, l;
                packsplit(acc[i][j][0] * scl, acc[i][j][1] * scl, h, l);
                *(uint32_t*)&Ch[(size_t)row * D_MODEL + col] = h;
                *(uint32_t*)&Cl[(size_t)row * D_MODEL + col] = l;
                packsplit(acc[i][j][2] * scl, acc[i][j][3] * scl, h, l);
                *(uint32_t*)&Ch[(size_t)(row + 8) * D_MODEL + col] = h;
                *(uint32_t*)&Cl[(size_t)(row + 8) * D_MODEL + col] = l;
            } else {            // high-only output (K, V)
                *(uint32_t*)&Ch[(size_t)row * D_MODEL + col] =
                    packhi(acc[i][j][0], acc[i][j][1]);
                *(uint32_t*)&Ch[(size_t)(row + 8) * D_MODEL + col] =
                    packhi(acc[i][j][2], acc[i][j][3]);
            }
        }
    }
}

// Q pre-scale folds softmax scale AND log2(e) so attention can use exp2:
#define QSCALE 0.18033688011112042f   // 0.125 * 1.4426950408889634

__global__ void __launch_bounds__(256, 2)
gemm_qkv() {
    const int z = blockIdx.z;
    if (z == 0)
        gemm_core<true >(g_WH, nullptr, g_QH, g_QL, QSCALE);
    else if (z == 1)
        gemm_core<false>(g_WH + DD, nullptr, g_KH, nullptr, 1.f);
    else
        gemm_core<false>(g_WH + 2ull * DD, nullptr, g_VH, nullptr, 1.f);
}
__global__ void __launch_bounds__(256, 2)
gemm_o(float* __restrict__ out) {
    gemm_core<true>(g_WH + 3ull * DD, out, nullptr, nullptr, 1.f);
}

// ---------------------------------------------------------------------------
// Tensor-core causal flash attention (R13, proven). S = (Qh+Ql)·Kh;
// O += Ph·Vh. Softmax in log2 domain (ex2.approx). 3-stage KV pipeline.
// ---------------------------------------------------------------------------
#define AST 16640
#define SM_ATTN (3 * AST)    // 49920

__global__ void __launch_bounds__(128, 3)
attn_mma(const int* __restrict__ mask)
{
    extern __shared__ char smem[];
    const uint32_t sb = smem_u32(smem);
    const int tid = threadIdx.x, wid = tid >> 5, lid = tid & 31;
    const int qt = gridDim.x - 1 - blockIdx.x;      // LPT: heavy blocks first
    const int h = blockIdx.y, b = blockIdx.z;
    const int bm = qt * 64;
    const int nt = qt + 1;                // causal: key tiles 0..qt

    // ---- stage Q (QH|QL) into the stage area, extract fragments ----
    {
#pragma unroll
        for (int u = 0; u < 8; u++) {
            const int i = tid + u * 128;          // 0..1023
            const int arr = i >> 9;               // 0 QH, 1 QL
            const int j = i & 511;
            const int r = j >> 3, c = j & 7;
            const __half* src = (arr ? g_QL : g_QH) +
                (size_t)(b * SEQ + bm + r) * D_MODEL + h * HEAD_DIM + c * 8;
            cp_async16(sb + (uint32_t)arr * 8192 +
                       (uint32_t)r * 128 + (uint32_t)((c ^ (r & 7)) << 4), src);
        }
        cp_commit();
        cp_wait<0>();
        __syncthreads();
    }
    uint32_t aQh[4][4], aQl[4][4];
#pragma unroll
    for (int ks = 0; ks < 4; ks++) {
        const uint32_t off = (uint32_t)(wid * 16 + (lid & 15)) * 128 +
                             (uint32_t)(((2 * ks + (lid >> 4)) ^ (lid & 7)) << 4);
        ldsm_x4(sb + off, aQh[ks]);
        ldsm_x4(sb + 8192 + off, aQl[ks]);
    }
    __syncthreads();          // Q extracted; area reused for KV stages

    auto issueKV = [&](int ti) {
        const uint32_t st = sb + (uint32_t)(ti % 3) * AST;
        const int t0 = ti * 64;
#pragma unroll
        for (int u = 0; u < 8; u++) {
            const int i = tid + u * 128;          // 0..1023
            const int arr = i >> 9;               // 0 Kh, 1 Vh
            const int j = i & 511;
            const int r = j >> 3, c = j & 7;
            const __half* base = arr ? g_VH : g_KH;
            const __half* src = base +
                (size_t)(b * SEQ + t0 + r) * D_MODEL + h * HEAD_DIM + c * 8;
            cp_async16(st + (uint32_t)arr * 8192 +
                       (uint32_t)r * 128 + (uint32_t)((c ^ (r & 7)) << 4), src);
        }
        if (tid < 16)
            cp_async16(st + 16384 + tid * 16, mask + b * SEQ + t0 + tid * 4);
        cp_commit();
    };

    issueKV(0);
    if (nt > 1) issueKV(1);
    if (nt > 2) issueKV(2);

    float oreg[8][4];
#pragma unroll
    for (int j = 0; j < 8; j++)
#pragma unroll
        for (int q = 0; q < 4; q++) oreg[j][q] = 0.f;
    float mA = -1e30f, mB = -1e30f, lA = 0.f, lB = 0.f;
    const int q0 = bm + wid * 16 + (lid >> 2);

#pragma unroll 1
    for (int ti = 0; ti < nt; ti++) {
        const int rem = nt - ti;
        if (rem > 2)      cp_wait<2>();
        else if (rem == 2) cp_wait<1>();
        else               cp_wait<0>();
        __syncthreads();
        const uint32_t st = sb + (uint32_t)(ti % 3) * AST;
        const int* msk_s = (const int*)(smem + (ti % 3) * AST + 16384);
        const int t0 = ti * 64;

        // ---- S(log2) = (Qh + Ql) @ Kh^T ----
        float sr[8][4];
#pragma unroll
        for (int j = 0; j < 8; j++)
#pragma unroll
            for (int q = 0; q < 4; q++) sr[j][q] = 0.f;
#pragma unroll
        for (int ks = 0; ks < 4; ks++) {
            uint32_t bh[4][4];
#pragma unroll
            for (int nb = 0; nb < 4; nb++) {
                const uint32_t row = (uint32_t)(nb * 16 + (lid & 7) + ((lid >> 4) & 1) * 8);
                const uint32_t off = row * 128 +
                    (uint32_t)(((2 * ks + ((lid >> 3) & 1)) ^ (lid & 7)) << 4);
                ldsm_x4(st + off, bh[nb]);
            }
#pragma unroll
            for (int j = 0; j < 8; j++) {
                const uint32_t b0 = bh[j >> 1][(j & 1) * 2], b1 = bh[j >> 1][(j & 1) * 2 + 1];
                mma16816(sr[j], aQh[ks], b0, b1);
                mma16816(sr[j], aQl[ks], b0, b1);
            }
        }

        // ---- mask + online softmax (log2 domain) ----
        const bool diag = (ti == qt);
#pragma unroll
        for (int j = 0; j < 8; j++) {
            const int c = j * 8 + (lid & 3) * 2;
            const int kg = t0 + c;
            const int mk0 = msk_s[c], mk1 = msk_s[c + 1];
            if (!mk0) { sr[j][0] = -1e30f; sr[j][2] = -1e30f; }
            if (!mk1) { sr[j][1] = -1e30f; sr[j][3] = -1e30f; }
            if (diag) {
                if (kg     > q0)     sr[j][0] = -1e30f;
                if (kg + 1 > q0)     sr[j][1] = -1e30f;
                if (kg     > q0 + 8) sr[j][2] = -1e30f;
                if (kg + 1 > q0 + 8) sr[j][3] = -1e30f;
            }
        }
        float tmA = -1e30f, tmB = -1e30f;
#pragma unroll
        for (int j = 0; j < 8; j++) {
            tmA = fmaxf(tmA, fmaxf(sr[j][0], sr[j][1]));
            tmB = fmaxf(tmB, fmaxf(sr[j][2], sr[j][3]));
        }
        tmA = fmaxf(tmA, __shfl_xor_sync(0xffffffff, tmA, 1));
        tmA = fmaxf(tmA, __shfl_xor_sync(0xffffffff, tmA, 2));
        tmB = fmaxf(tmB, __shfl_xor_sync(0xffffffff, tmB, 1));
        tmB = fmaxf(tmB, __shfl_xor_sync(0xffffffff, tmB, 2));
        const float nmA = fmaxf(mA, tmA), nmB = fmaxf(mB, tmB);
        const float corrA = ex2f(mA - nmA), corrB = ex2f(mB - nmB);
        mA = nmA; mB = nmB;
        float sA = 0.f, sB = 0.f;
#pragma unroll
        for (int j = 0; j < 8; j++) {
            sr[j][0] = ex2f(sr[j][0] - nmA);
            sr[j][1] = ex2f(sr[j][1] - nmA);
            sr[j][2] = ex2f(sr[j][2] - nmB);
            sr[j][3] = ex2f(sr[j][3] - nmB);
            sA += sr[j][0] + sr[j][1];
            sB += sr[j][2] + sr[j][3];
        }
        sA += __shfl_xor_sync(0xffffffff, sA, 1);
        sA += __shfl_xor_sync(0xffffffff, sA, 2);
        sB += __shfl_xor_sync(0xffffffff, sB, 1);
        sB += __shfl_xor_sync(0xffffffff, sB, 2);
        lA = lA * corrA + sA;
        lB = lB * corrB + sB;
#pragma unroll
        for (int j = 0; j < 8; j++) {
            oreg[j][0] *= corrA; oreg[j][1] *= corrA;
            oreg[j][2] *= corrB; oreg[j][3] *= corrB;
        }

        // ---- O += Ph @ Vh (single term) ----
#pragma unroll
        for (int ks = 0; ks < 4; ks++) {
            uint32_t aph[4];
            aph[0] = packhi(sr[2*ks][0],   sr[2*ks][1]);
            aph[1] = packhi(sr[2*ks][2],   sr[2*ks][3]);
            aph[2] = packhi(sr[2*ks+1][0], sr[2*ks+1][1]);
            aph[3] = packhi(sr[2*ks+1][2], sr[2*ks+1][3]);
            uint32_t vh[4][4];
#pragma unroll
            for (int nb = 0; nb < 4; nb++) {
                const uint32_t row = (uint32_t)(ks * 16 + (lid & 7) + ((lid >> 3) & 1) * 8);
                const uint32_t chk = (uint32_t)(nb * 2 + (lid >> 4));
                const uint32_t off = row * 128 + ((chk ^ (lid & 7)) << 4);
                ldsm_x4t(st + 8192 + off, vh[nb]);
            }
#pragma unroll
            for (int j = 0; j < 8; j++) {
                const uint32_t b0 = vh[j >> 1][(j & 1) * 2], b1 = vh[j >> 1][(j & 1) * 2 + 1];
                mma16816(oreg[j], aph, b0, b1);
            }
        }

        __syncthreads();
        if (ti + 3 < nt) issueKV(ti + 3);
    }

    // ---- epilogue: normalize, split to fp16 h/l for the O-GEMM ----
    const float invA = 1.f / lA, invB = 1.f / lB;
    const size_t rA = (size_t)(b * SEQ + q0) * D_MODEL + h * HEAD_DIM;
    const size_t rB = rA + 8ull * D_MODEL;
#pragma unroll
    for (int j = 0; j < 8; j++) {
        const int col = j * 8 + (lid & 3) * 2;
        uint32_t hh, ll;
        packsplit(oreg[j][0] * invA, oreg[j][1] * invA, hh, ll);
        *(uint32_t*)&g_XH[rA + col] = hh;
        *(uint32_t*)&g_XL[rA + col] = ll;
        packsplit(oreg[j][2] * invB, oreg[j][3] * invB, hh, ll);
        *(uint32_t*)&g_XH[rB + col] = hh;
        *(uint32_t*)&g_XL[rB + col] = ll;
    }
}

// ---------------------------------------------------------------------------
// Launch. Inputs: x, attention_mask, wq, wk, wv, wo. Output fp32.
// ---------------------------------------------------------------------------
extern "C" void kernel_launch(void* const* d_in, const int* in_sizes, int n_in,
                              void* d_out, int out_size)
{
    const float* x    = (const float*)d_in[0];
    const int*   amsk = (const int*)  d_in[1];
    const float* wq   = (const float*)d_in[2];
    const float* wk   = (const float*)d_in[3];
    const float* wv   = (const float*)d_in[4];
    const float* wo   = (const float*)d_in[5];
    float*       out  = (float*)d_out;

    cudaFuncSetAttribute(gemm_qkv, cudaFuncAttributeMaxDynamicSharedMemorySize, SM_GEMM);
    cudaFuncSetAttribute(gemm_o,   cudaFuncAttributeMaxDynamicSharedMemorySize, SM_GEMM);
    cudaFuncSetAttribute(attn_mma, cudaFuncAttributeMaxDynamicSharedMemorySize, SM_ATTN);

    conv_all<<<dim3(2048, 1, 6), 256>>>(x, wq, wk, wv, wo);

    dim3 gQKV(D_MODEL / 128, M_ROWS / 128, 3);   // (8, 64, 3)
    gemm_qkv<<<gQKV, 256, SM_GEMM>>>();

    dim3 gAttn(SEQ / 64, N_HEADS, BATCH);        // (32, 16, 4)
    attn_mma<<<gAttn, 128, SM_ATTN>>>(amsk);

    dim3 gOut(D_MODEL / 128, M_ROWS / 128, 1);
    gemm_o<<<gOut, 256, SM_GEMM>>>(out);
}

// round 15
// speedup vs baseline: 3.1975x; 1.0940x over previous
#include <cuda_runtime.h>
#include <cuda_fp16.h>
#include <cstdint>
#include <math.h>

#define D_MODEL  1024
#define N_HEADS  16
#define HEAD_DIM 64
#define BATCH    4
#define SEQ      2048
#define M_ROWS   (BATCH * SEQ)   // 8192
#define DD       (D_MODEL * D_MODEL)

// ---------------------------------------------------------------------------
// Static scratch. fp16 2-term splits: only Q and X/AO need low parts.
// ---------------------------------------------------------------------------
__device__ __half g_QH[M_ROWS * D_MODEL];
__device__ __half g_QL[M_ROWS * D_MODEL];
__device__ __half g_KH[M_ROWS * D_MODEL];
__device__ __half g_VH[M_ROWS * D_MODEL];
__device__ __half g_XH[M_ROWS * D_MODEL];   // x, then attn-out (hi)
__device__ __half g_XL[M_ROWS * D_MODEL];   // x, then attn-out (lo)
__device__ __half g_WH[4 * DD];             // wq,wk,wv,wo hi
__device__ __half g_WL[4 * DD];             // wq,wk,wv,wo lo

// ---------------------------------------------------------------------------
// Helpers (compute_103-safe)
// ---------------------------------------------------------------------------
__device__ __forceinline__ uint32_t smem_u32(const void* p) {
    uint32_t a;
    asm("{ .reg .u64 t; cvta.to.shared.u64 t, %1; cvt.u32.u64 %0, t; }"
        : "=r"(a) : "l"(p));
    return a;
}
__device__ __forceinline__ float ex2f(float x) {
    float r;
    asm("ex2.approx.f32 %0, %1;" : "=f"(r) : "f"(x));
    return r;
}
__device__ __forceinline__ void cp_async16(uint32_t dst, const void* src) {
    asm volatile("cp.async.cg.shared.global [%0], [%1], 16;\n"
                 :: "r"(dst), "l"(src) : "memory");
}
__device__ __forceinline__ void cp_commit() {
    asm volatile("cp.async.commit_group;\n" ::: "memory");
}
template <int N>
__device__ __forceinline__ void cp_wait() {
    asm volatile("cp.async.wait_group %0;\n" :: "n"(N) : "memory");
}
__device__ __forceinline__ void ldsm_x4(uint32_t addr, uint32_t* r) {
    asm volatile("ldmatrix.sync.aligned.m8n8.x4.shared.b16 {%0,%1,%2,%3}, [%4];\n"
                 : "=r"(r[0]), "=r"(r[1]), "=r"(r[2]), "=r"(r[3]) : "r"(addr));
}
__device__ __forceinline__ void ldsm_x4t(uint32_t addr, uint32_t* r) {
    asm volatile("ldmatrix.sync.aligned.m8n8.x4.trans.shared.b16 {%0,%1,%2,%3}, [%4];\n"
                 : "=r"(r[0]), "=r"(r[1]), "=r"(r[2]), "=r"(r[3]) : "r"(addr));
}
__device__ __forceinline__ void mma16816(float* c, const uint32_t* a,
                                         uint32_t b0, uint32_t b1) {
    asm volatile(
        "mma.sync.aligned.m16n8k16.row.col.f32.f16.f16.f32 "
        "{%0,%1,%2,%3}, {%4,%5,%6,%7}, {%8,%9}, {%0,%1,%2,%3};\n"
        : "+f"(c[0]), "+f"(c[1]), "+f"(c[2]), "+f"(c[3])
        : "r"(a[0]), "r"(a[1]), "r"(a[2]), "r"(a[3]), "r"(b0), "r"(b1));
}
__device__ __forceinline__ void packsplit(float x, float y,
                                          uint32_t& hi, uint32_t& lo) {
    __half2 H = __floats2half2_rn(x, y);
    float2 Hf = __half22float2(H);
    __half2 L = __floats2half2_rn(x - Hf.x, y - Hf.y);
    hi = *(uint32_t*)&H;
    lo = *(uint32_t*)&L;
}
__device__ __forceinline__ uint32_t packhi(float x, float y) {
    __half2 H = __floats2half2_rn(x, y);
    return *(uint32_t*)&H;
}

// ---------------------------------------------------------------------------
// Merged split conversion: z 0..3 -> quarters of x, z=4 -> wq|wk, z=5 -> wv|wo
// ---------------------------------------------------------------------------
__device__ __forceinline__ void split4(float4 v, __half* h, __half* l,
                                       size_t idx4) {
    uint32_t h0, l0, h1, l1;
    packsplit(v.x, v.y, h0, l0);
    packsplit(v.z, v.w, h1, l1);
    ((uint32_t*)h)[idx4 * 2 + 0] = h0;
    ((uint32_t*)h)[idx4 * 2 + 1] = h1;
    ((uint32_t*)l)[idx4 * 2 + 0] = l0;
    ((uint32_t*)l)[idx4 * 2 + 1] = l1;
}
__global__ void conv_all(const float* __restrict__ x,
                         const float* __restrict__ w0, const float* __restrict__ w1,
                         const float* __restrict__ w2, const float* __restrict__ w3)
{
    const int z = blockIdx.z;
    const size_t bx = blockIdx.x;                      // 0..2047
    const size_t li = bx * blockDim.x + threadIdx.x;   // 0..524287 (float4 idx)
    if (z < 4) {
        const size_t i = (size_t)z * 524288 + li;      // x: 2M float4 total
        split4(((const float4*)x)[i], g_XH, g_XL, i);
    } else {
        const int wsel = (z - 4) * 2 + (int)(li >> 18);    // 0..3
        const size_t i = li & 262143;                      // DD/4 = 262144
        const float* w = (wsel == 0) ? w0 : (wsel == 1) ? w1
                       : (wsel == 2) ? w2 : w3;
        split4(((const float4*)w)[i], g_WH + (size_t)wsel * DD,
               g_WL + (size_t)wsel * DD, i);
    }
}

// ---------------------------------------------------------------------------
// Split-fp16 GEMM, templated term count.
// TWO=true : C = Ah*Bh + Al*Bh. 2-stage pipeline, stage = Ah|Al|B (48KB).
// TWO=false: C = Ah*Bh.         3-stage pipeline, stage = Ah|B (32KB).
// Both total 96KB smem -> 2 CTAs/SM.
// ---------------------------------------------------------------------------
#define BK      64
#define NKT     (D_MODEL / BK)    // 16
#define A_BYTES (128 * 128)       // 16384
#define SM_GEMM (6 * A_BYTES)     // 98304

template <bool TWO>
__device__ __forceinline__ void gemm_core(const __half* __restrict__ Bh,
                                          float* __restrict__ Cf,
                                          __half* __restrict__ Ch,
                                          __half* __restrict__ Cl,
                                          float scl)
{
    extern __shared__ char smem[];
    const uint32_t sb = smem_u32(smem);
    const int tid = threadIdx.x;
    const int wid = tid >> 5, lid = tid & 31;
    const int wm  = wid >> 2, wn = wid & 3;
    const int bm  = blockIdx.y * 128, bn = blockIdx.x * 128;

    constexpr int NST     = TWO ? 2 : 3;                  // pipeline stages
    constexpr uint32_t SSTR = TWO ? 3u * A_BYTES : 2u * A_BYTES;  // stage stride
    constexpr uint32_t BOFF = TWO ? 2u * A_BYTES : 1u * A_BYTES;  // B offset in stage

    const int llo  = lid & 7;
    const int lr15 = lid & 15;
    const int lhiA = lid >> 4;
    const int lk8B = (lid >> 3) & 1;
    uint32_t aRow[4], bRow[2];
#pragma unroll
    for (int i = 0; i < 4; i++) aRow[i] = (uint32_t)(wm * 64 + i * 16 + lr15) * 128;
#pragma unroll
    for (int p = 0; p < 2; p++)
        bRow[p] = (uint32_t)(wn * 32 + p * 16 + llo + ((lid >> 4) & 1) * 8) * 128;

    float acc[4][4][4];
#pragma unroll
    for (int i = 0; i < 4; i++)
#pragma unroll
        for (int j = 0; j < 4; j++)
#pragma unroll
            for (int q = 0; q < 4; q++) acc[i][j][q] = 0.f;

    auto issue = [&](int kt) {
        const uint32_t st = sb + (uint32_t)(kt % NST) * SSTR;
        const int k0 = kt * BK;
        constexpr int NCH = TWO ? 12 : 8;       // 16B chunks per thread
#pragma unroll
        for (int u = 0; u < NCH; u++) {
            const int i = tid + u * 256;
            const int arr = i >> 10;            // TWO: 0 Ah,1 Al,2 B ; else 0 Ah,1 B
            const int j = i & 1023;
            const int r = j >> 3, c = j & 7;
            const __half* src;
            uint32_t dstOff;
            if (TWO) {
                src = (arr == 0) ? g_XH + (size_t)(bm + r) * D_MODEL + k0 + c * 8
                    : (arr == 1) ? g_XL + (size_t)(bm + r) * D_MODEL + k0 + c * 8
                                 : Bh   + (size_t)(bn + r) * D_MODEL + k0 + c * 8;
                dstOff = (uint32_t)arr * A_BYTES;
            } else {
                src = (arr == 0) ? g_XH + (size_t)(bm + r) * D_MODEL + k0 + c * 8
                                 : Bh   + (size_t)(bn + r) * D_MODEL + k0 + c * 8;
                dstOff = (arr == 0) ? 0u : BOFF;
            }
            const uint32_t dst = st + dstOff +
                                 (uint32_t)r * 128 + (uint32_t)((c ^ (r & 7)) << 4);
            cp_async16(dst, src);
        }
        cp_commit();
    };

    issue(0);
    issue(1);
    if (!TWO) issue(2);

#pragma unroll 1
    for (int t = 0; t < NKT; t++) {
        const int rem = NKT - t;
        if (rem > NST - 1)       cp_wait<NST - 1>();
        else if (rem == 2)       cp_wait<1>();
        else                     cp_wait<0>();
        __syncthreads();

        const uint32_t st = sb + (uint32_t)(t % NST) * SSTR;
#pragma unroll
        for (int s = 0; s < 4; s++) {
            const uint32_t offA = (uint32_t)(((2 * s + lhiA) ^ llo) << 4);
            const uint32_t offB = (uint32_t)(((2 * s + lk8B) ^ llo) << 4);
            uint32_t b[2][4];
#pragma unroll
            for (int p = 0; p < 2; p++)
                ldsm_x4(st + BOFF + bRow[p] + offB, b[p]);

            uint32_t ah[4][4];
#pragma unroll
            for (int i = 0; i < 4; i++) ldsm_x4(st + aRow[i] + offA, ah[i]);
#pragma unroll
            for (int i = 0; i < 4; i++)
#pragma unroll
                for (int j = 0; j < 4; j++)
                    mma16816(acc[i][j], ah[i], b[j >> 1][(j & 1) * 2 + 0],
                                               b[j >> 1][(j & 1) * 2 + 1]);

            if (TWO) {
                uint32_t al[4][4];
#pragma unroll
                for (int i = 0; i < 4; i++)
                    ldsm_x4(st + A_BYTES + aRow[i] + offA, al[i]);
#pragma unroll
                for (int i = 0; i < 4; i++)
#pragma unroll
                    for (int j = 0; j < 4; j++)
                        mma16816(acc[i][j], al[i], b[j >> 1][(j & 1) * 2 + 0],
                                                   b[j >> 1][(j & 1) * 2 + 1]);
            }
        }
        __syncthreads();
        if (t + NST < NKT) issue(t + NST);
    }

    const int g  = lid >> 2;
    const int t2 = (lid & 3) * 2;
#pragma unroll
    for (int i = 0; i < 4; i++) {
        const int row = bm + wm * 64 + i * 16 + g;
#pragma unroll
        for (int j = 0; j < 4; j++) {
            const int col = bn + wn * 32 + j * 8 + t2;
            if (Cf) {
                *(float2*)&Cf[(size_t)row * D_MODEL + col] =
                    make_float2(acc[i][j][0], acc[i][j][1]);
                *(float2*)&Cf[(size_t)(row + 8) * D_MODEL + col] =
                    make_float2(acc[i][j][2], acc[i][j][3]);
            } else if (Cl) {    // split output (Q)
                uint32_t h, l;
                packsplit(acc[i][j][0] * scl, acc[i][j][1] * scl, h, l);
                *(uint32_t*)&Ch[(size_t)row * D_MODEL + col] = h;
                *(uint32_t*)&Cl[(size_t)row * D_MODEL + col] = l;
                packsplit(acc[i][j][2] * scl, acc[i][j][3] * scl, h, l);
                *(uint32_t*)&Ch[(size_t)(row + 8) * D_MODEL + col] = h;
                *(uint32_t*)&Cl[(size_t)(row + 8) * D_MODEL + col] = l;
            } else {            // high-only output (K, V)
                *(uint32_t*)&Ch[(size_t)row * D_MODEL + col] =
                    packhi(acc[i][j][0], acc[i][j][1]);
                *(uint32_t*)&Ch[(size_t)(row + 8) * D_MODEL + col] =
                    packhi(acc[i][j][2], acc[i][j][3]);
            }
        }
    }
}

// Q pre-scale folds softmax scale AND log2(e) so attention can use exp2:
#define QSCALE 0.18033688011112042f   // 0.125 * 1.4426950408889634

__global__ void __launch_bounds__(256, 2)
gemm_qkv() {
    const int z = blockIdx.z;
    if (z == 0)
        gemm_core<true >(g_WH, nullptr, g_QH, g_QL, QSCALE);
    else if (z == 1)
        gemm_core<false>(g_WH + DD, nullptr, g_KH, nullptr, 1.f);
    else
        gemm_core<false>(g_WH + 2ull * DD, nullptr, g_VH, nullptr, 1.f);
}
__global__ void __launch_bounds__(256, 2)
gemm_o(float* __restrict__ out) {
    // single-term: AO's fp16 low part is below AO's own upstream error floor
    gemm_core<false>(g_WH + 3ull * DD, out, nullptr, nullptr, 1.f);
}

// ---------------------------------------------------------------------------
// Tensor-core causal flash attention (R13, proven). S = (Qh+Ql)·Kh;
// O += Ph·Vh. Softmax in log2 domain (ex2.approx). 3-stage KV pipeline.
// ---------------------------------------------------------------------------
#define AST 16640
#define SM_ATTN (3 * AST)    // 49920

__global__ void __launch_bounds__(128, 3)
attn_mma(const int* __restrict__ mask)
{
    extern __shared__ char smem[];
    const uint32_t sb = smem_u32(smem);
    const int tid = threadIdx.x, wid = tid >> 5, lid = tid & 31;
    const int qt = gridDim.x - 1 - blockIdx.x;      // LPT: heavy blocks first
    const int h = blockIdx.y, b = blockIdx.z;
    const int bm = qt * 64;
    const int nt = qt + 1;                // causal: key tiles 0..qt

    // ---- stage Q (QH|QL) into the stage area, extract fragments ----
    {
#pragma unroll
        for (int u = 0; u < 8; u++) {
            const int i = tid + u * 128;          // 0..1023
            const int arr = i >> 9;               // 0 QH, 1 QL
            const int j = i & 511;
            const int r = j >> 3, c = j & 7;
            const __half* src = (arr ? g_QL : g_QH) +
                (size_t)(b * SEQ + bm + r) * D_MODEL + h * HEAD_DIM + c * 8;
            cp_async16(sb + (uint32_t)arr * 8192 +
                       (uint32_t)r * 128 + (uint32_t)((c ^ (r & 7)) << 4), src);
        }
        cp_commit();
        cp_wait<0>();
        __syncthreads();
    }
    uint32_t aQh[4][4], aQl[4][4];
#pragma unroll
    for (int ks = 0; ks < 4; ks++) {
        const uint32_t off = (uint32_t)(wid * 16 + (lid & 15)) * 128 +
                             (uint32_t)(((2 * ks + (lid >> 4)) ^ (lid & 7)) << 4);
        ldsm_x4(sb + off, aQh[ks]);
        ldsm_x4(sb + 8192 + off, aQl[ks]);
    }
    __syncthreads();          // Q extracted; area reused for KV stages

    auto issueKV = [&](int ti) {
        const uint32_t st = sb + (uint32_t)(ti % 3) * AST;
        const int t0 = ti * 64;
#pragma unroll
        for (int u = 0; u < 8; u++) {
            const int i = tid + u * 128;          // 0..1023
            const int arr = i >> 9;               // 0 Kh, 1 Vh
            const int j = i & 511;
            const int r = j >> 3, c = j & 7;
            const __half* base = arr ? g_VH : g_KH;
            const __half* src = base +
                (size_t)(b * SEQ + t0 + r) * D_MODEL + h * HEAD_DIM + c * 8;
            cp_async16(st + (uint32_t)arr * 8192 +
                       (uint32_t)r * 128 + (uint32_t)((c ^ (r & 7)) << 4), src);
        }
        if (tid < 16)
            cp_async16(st + 16384 + tid * 16, mask + b * SEQ + t0 + tid * 4);
        cp_commit();
    };

    issueKV(0);
    if (nt > 1) issueKV(1);
    if (nt > 2) issueKV(2);

    float oreg[8][4];
#pragma unroll
    for (int j = 0; j < 8; j++)
#pragma unroll
        for (int q = 0; q < 4; q++) oreg[j][q] = 0.f;
    float mA = -1e30f, mB = -1e30f, lA = 0.f, lB = 0.f;
    const int q0 = bm + wid * 16 + (lid >> 2);

#pragma unroll 1
    for (int ti = 0; ti < nt; ti++) {
        const int rem = nt - ti;
        if (rem > 2)      cp_wait<2>();
        else if (rem == 2) cp_wait<1>();
        else               cp_wait<0>();
        __syncthreads();
        const uint32_t st = sb + (uint32_t)(ti % 3) * AST;
        const int* msk_s = (const int*)(smem + (ti % 3) * AST + 16384);
        const int t0 = ti * 64;

        // ---- S(log2) = (Qh + Ql) @ Kh^T ----
        float sr[8][4];
#pragma unroll
        for (int j = 0; j < 8; j++)
#pragma unroll
            for (int q = 0; q < 4; q++) sr[j][q] = 0.f;
#pragma unroll
        for (int ks = 0; ks < 4; ks++) {
            uint32_t bh[4][4];
#pragma unroll
            for (int nb = 0; nb < 4; nb++) {
                const uint32_t row = (uint32_t)(nb * 16 + (lid & 7) + ((lid >> 4) & 1) * 8);
                const uint32_t off = row * 128 +
                    (uint32_t)(((2 * ks + ((lid >> 3) & 1)) ^ (lid & 7)) << 4);
                ldsm_x4(st + off, bh[nb]);
            }
#pragma unroll
            for (int j = 0; j < 8; j++) {
                const uint32_t b0 = bh[j >> 1][(j & 1) * 2], b1 = bh[j >> 1][(j & 1) * 2 + 1];
                mma16816(sr[j], aQh[ks], b0, b1);
                mma16816(sr[j], aQl[ks], b0, b1);
            }
        }

        // ---- mask + online softmax (log2 domain) ----
        const bool diag = (ti == qt);
#pragma unroll
        for (int j = 0; j < 8; j++) {
            const int c = j * 8 + (lid & 3) * 2;
            const int kg = t0 + c;
            const int mk0 = msk_s[c], mk1 = msk_s[c + 1];
            if (!mk0) { sr[j][0] = -1e30f; sr[j][2] = -1e30f; }
            if (!mk1) { sr[j][1] = -1e30f; sr[j][3] = -1e30f; }
            if (diag) {
                if (kg     > q0)     sr[j][0] = -1e30f;
                if (kg + 1 > q0)     sr[j][1] = -1e30f;
                if (kg     > q0 + 8) sr[j][2] = -1e30f;
                if (kg + 1 > q0 + 8) sr[j][3] = -1e30f;
            }
        }
        float tmA = -1e30f, tmB = -1e30f;
#pragma unroll
        for (int j = 0; j < 8; j++) {
            tmA = fmaxf(tmA, fmaxf(sr[j][0], sr[j][1]));
            tmB = fmaxf(tmB, fmaxf(sr[j][2], sr[j][3]));
        }
        tmA = fmaxf(tmA, __shfl_xor_sync(0xffffffff, tmA, 1));
        tmA = fmaxf(tmA, __shfl_xor_sync(0xffffffff, tmA, 2));
        tmB = fmaxf(tmB, __shfl_xor_sync(0xffffffff, tmB, 1));
        tmB = fmaxf(tmB, __shfl_xor_sync(0xffffffff, tmB, 2));
        const float nmA = fmaxf(mA, tmA), nmB = fmaxf(mB, tmB);
        const float corrA = ex2f(mA - nmA), corrB = ex2f(mB - nmB);
        mA = nmA; mB = nmB;
        float sA = 0.f, sB = 0.f;
#pragma unroll
        for (int j = 0; j < 8; j++) {
            sr[j][0] = ex2f(sr[j][0] - nmA);
            sr[j][1] = ex2f(sr[j][1] - nmA);
            sr[j][2] = ex2f(sr[j][2] - nmB);
            sr[j][3] = ex2f(sr[j][3] - nmB);
            sA += sr[j][0] + sr[j][1];
            sB += sr[j][2] + sr[j][3];
        }
        sA += __shfl_xor_sync(0xffffffff, sA, 1);
        sA += __shfl_xor_sync(0xffffffff, sA, 2);
        sB += __shfl_xor_sync(0xffffffff, sB, 1);
        sB += __shfl_xor_sync(0xffffffff, sB, 2);
        lA = lA * corrA + sA;
        lB = lB * corrB + sB;
#pragma unroll
        for (int j = 0; j < 8; j++) {
            oreg[j][0] *= corrA; oreg[j][1] *= corrA;
            oreg[j][2] *= corrB; oreg[j][3] *= corrB;
        }

        // ---- O += Ph @ Vh (single term) ----
#pragma unroll
        for (int ks = 0; ks < 4; ks++) {
            uint32_t aph[4];
            aph[0] = packhi(sr[2*ks][0],   sr[2*ks][1]);
            aph[1] = packhi(sr[2*ks][2],   sr[2*ks][3]);
            aph[2] = packhi(sr[2*ks+1][0], sr[2*ks+1][1]);
            aph[3] = packhi(sr[2*ks+1][2], sr[2*ks+1][3]);
            uint32_t vh[4][4];
#pragma unroll
            for (int nb = 0; nb < 4; nb++) {
                const uint32_t row = (uint32_t)(ks * 16 + (lid & 7) + ((lid >> 3) & 1) * 8);
                const uint32_t chk = (uint32_t)(nb * 2 + (lid >> 4));
                const uint32_t off = row * 128 + ((chk ^ (lid & 7)) << 4);
                ldsm_x4t(st + 8192 + off, vh[nb]);
            }
#pragma unroll
            for (int j = 0; j < 8; j++) {
                const uint32_t b0 = vh[j >> 1][(j & 1) * 2], b1 = vh[j >> 1][(j & 1) * 2 + 1];
                mma16816(oreg[j], aph, b0, b1);
            }
        }

        __syncthreads();
        if (ti + 3 < nt) issueKV(ti + 3);
    }

    // ---- epilogue: normalize, split to fp16 h/l for the O-GEMM ----
    const float invA = 1.f / lA, invB = 1.f / lB;
    const size_t rA = (size_t)(b * SEQ + q0) * D_MODEL + h * HEAD_DIM;
    const size_t rB = rA + 8ull * D_MODEL;
#pragma unroll
    for (int j = 0; j < 8; j++) {
        const int col = j * 8 + (lid & 3) * 2;
        uint32_t hh, ll;
        packsplit(oreg[j][0] * invA, oreg[j][1] * invA, hh, ll);
        *(uint32_t*)&g_XH[rA + col] = hh;
        *(uint32_t*)&g_XL[rA + col] = ll;
        packsplit(oreg[j][2] * invB, oreg[j][3] * invB, hh, ll);
        *(uint32_t*)&g_XH[rB + col] = hh;
        *(uint32_t*)&g_XL[rB + col] = ll;
    }
}

// ---------------------------------------------------------------------------
// Launch. Inputs: x, attention_mask, wq, wk, wv, wo. Output fp32.
// ---------------------------------------------------------------------------
extern "C" void kernel_launch(void* const* d_in, const int* in_sizes, int n_in,
                              void* d_out, int out_size)
{
    const float* x    = (const float*)d_in[0];
    const int*   amsk = (const int*)  d_in[1];
    const float* wq   = (const float*)d_in[2];
    const float* wk   = (const float*)d_in[3];
    const float* wv   = (const float*)d_in[4];
    const float* wo   = (const float*)d_in[5];
    float*       out  = (float*)d_out;

    cudaFuncSetAttribute(gemm_qkv, cudaFuncAttributeMaxDynamicSharedMemorySize, SM_GEMM);
    cudaFuncSetAttribute(gemm_o,   cudaFuncAttributeMaxDynamicSharedMemorySize, SM_GEMM);
    cudaFuncSetAttribute(attn_mma, cudaFuncAttributeMaxDynamicSharedMemorySize, SM_ATTN);

    conv_all<<<dim3(2048, 1, 6), 256>>>(x, wq, wk, wv, wo);

    dim3 gQKV(D_MODEL / 128, M_ROWS / 128, 3);   // (8, 64, 3)
    gemm_qkv<<<gQKV, 256, SM_GEMM>>>();

    dim3 gAttn(SEQ / 64, N_HEADS, BATCH);        // (32, 16, 4)
    attn_mma<<<gAttn, 128, SM_ATTN>>>(amsk);

    dim3 gOut(D_MODEL / 128, M_ROWS / 128, 1);
    gemm_o<<<gOut, 256, SM_GEMM>>>(out);
}

// round 16
// speedup vs baseline: 3.5310x; 1.1043x over previous
#include <cuda_runtime.h>
#include <cuda_fp16.h>
#include <cstdint>
#include <math.h>

#define D_MODEL  1024
#define N_HEADS  16
#define HEAD_DIM 64
#define BATCH    4
#define SEQ      2048
#define M_ROWS   (BATCH * SEQ)   // 8192
#define DD       (D_MODEL * D_MODEL)

// ---------------------------------------------------------------------------
// Static scratch. Only x keeps a low part (feeds the 2-term Q projection).
// ---------------------------------------------------------------------------
__device__ __half g_QH[M_ROWS * D_MODEL];
__device__ __half g_KH[M_ROWS * D_MODEL];
__device__ __half g_VH[M_ROWS * D_MODEL];
__device__ __half g_XH[M_ROWS * D_MODEL];   // x, then attn-out (hi)
__device__ __half g_XL[M_ROWS * D_MODEL];   // x lo (Q projection only)
__device__ __half g_WH[4 * DD];             // wq,wk,wv,wo hi

// ---------------------------------------------------------------------------
// Helpers (compute_103-safe)
// ---------------------------------------------------------------------------
__device__ __forceinline__ uint32_t smem_u32(const void* p) {
    uint32_t a;
    asm("{ .reg .u64 t; cvta.to.shared.u64 t, %1; cvt.u32.u64 %0, t; }"
        : "=r"(a) : "l"(p));
    return a;
}
__device__ __forceinline__ float ex2f(float x) {
    float r;
    asm("ex2.approx.f32 %0, %1;" : "=f"(r) : "f"(x));
    return r;
}
__device__ __forceinline__ void cp_async16(uint32_t dst, const void* src) {
    asm volatile("cp.async.cg.shared.global [%0], [%1], 16;\n"
                 :: "r"(dst), "l"(src) : "memory");
}
__device__ __forceinline__ void cp_commit() {
    asm volatile("cp.async.commit_group;\n" ::: "memory");
}
template <int N>
__device__ __forceinline__ void cp_wait() {
    asm volatile("cp.async.wait_group %0;\n" :: "n"(N) : "memory");
}
__device__ __forceinline__ void ldsm_x4(uint32_t addr, uint32_t* r) {
    asm volatile("ldmatrix.sync.aligned.m8n8.x4.shared.b16 {%0,%1,%2,%3}, [%4];\n"
                 : "=r"(r[0]), "=r"(r[1]), "=r"(r[2]), "=r"(r[3]) : "r"(addr));
}
__device__ __forceinline__ void ldsm_x4t(uint32_t addr, uint32_t* r) {
    asm volatile("ldmatrix.sync.aligned.m8n8.x4.trans.shared.b16 {%0,%1,%2,%3}, [%4];\n"
                 : "=r"(r[0]), "=r"(r[1]), "=r"(r[2]), "=r"(r[3]) : "r"(addr));
}
__device__ __forceinline__ void mma16816(float* c, const uint32_t* a,
                                         uint32_t b0, uint32_t b1) {
    asm volatile(
        "mma.sync.aligned.m16n8k16.row.col.f32.f16.f16.f32 "
        "{%0,%1,%2,%3}, {%4,%5,%6,%7}, {%8,%9}, {%0,%1,%2,%3};\n"
        : "+f"(c[0]), "+f"(c[1]), "+f"(c[2]), "+f"(c[3])
        : "r"(a[0]), "r"(a[1]), "r"(a[2]), "r"(a[3]), "r"(b0), "r"(b1));
}
__device__ __forceinline__ void packsplit(float x, float y,
                                          uint32_t& hi, uint32_t& lo) {
    __half2 H = __floats2half2_rn(x, y);
    float2 Hf = __half22float2(H);
    __half2 L = __floats2half2_rn(x - Hf.x, y - Hf.y);
    hi = *(uint32_t*)&H;
    lo = *(uint32_t*)&L;
}
__device__ __forceinline__ uint32_t packhi(float x, float y) {
    __half2 H = __floats2half2_rn(x, y);
    return *(uint32_t*)&H;
}

// ---------------------------------------------------------------------------
// Conversion: z 0..3 -> quarters of x (split h/l); z=4 -> wq|wk, z=5 -> wv|wo
// (weights hi-only: the GEMMs never read a W low part)
// ---------------------------------------------------------------------------
__global__ void conv_all(const float* __restrict__ x,
                         const float* __restrict__ w0, const float* __restrict__ w1,
                         const float* __restrict__ w2, const float* __restrict__ w3)
{
    const int z = blockIdx.z;
    const size_t bx = blockIdx.x;                      // 0..2047
    const size_t li = bx * blockDim.x + threadIdx.x;   // 0..524287 (float4 idx)
    if (z < 4) {
        const size_t i = (size_t)z * 524288 + li;
        float4 v = ((const float4*)x)[i];
        uint32_t h0, l0, h1, l1;
        packsplit(v.x, v.y, h0, l0);
        packsplit(v.z, v.w, h1, l1);
        ((uint32_t*)g_XH)[i * 2 + 0] = h0;
        ((uint32_t*)g_XH)[i * 2 + 1] = h1;
        ((uint32_t*)g_XL)[i * 2 + 0] = l0;
        ((uint32_t*)g_XL)[i * 2 + 1] = l1;
    } else {
        const int wsel = (z - 4) * 2 + (int)(li >> 18);    // 0..3
        const size_t i = li & 262143;                      // DD/4 = 262144
        const float* w = (wsel == 0) ? w0 : (wsel == 1) ? w1
                       : (wsel == 2) ? w2 : w3;
        float4 v = ((const float4*)w)[i];
        const size_t o = (size_t)wsel * DD / 4 + i;
        ((uint32_t*)g_WH)[o * 2 + 0] = packhi(v.x, v.y);
        ((uint32_t*)g_WH)[o * 2 + 1] = packhi(v.z, v.w);
    }
}

// ---------------------------------------------------------------------------
// Split-fp16 GEMM, templated term count.
// TWO=true : C = Ah*Bh + Al*Bh. 2-stage pipeline, stage = Ah|Al|B (48KB).
// TWO=false: C = Ah*Bh.         3-stage pipeline, stage = Ah|B (32KB).
// Output: fp32 (Cf) or fp16-high (Ch, scaled by scl).
// ---------------------------------------------------------------------------
#define BK      64
#define NKT     (D_MODEL / BK)    // 16
#define A_BYTES (128 * 128)       // 16384
#define SM_GEMM (6 * A_BYTES)     // 98304

template <bool TWO>
__device__ __forceinline__ void gemm_core(const __half* __restrict__ Bh,
                                          float* __restrict__ Cf,
                                          __half* __restrict__ Ch,
                                          float scl)
{
    extern __shared__ char smem[];
    const uint32_t sb = smem_u32(smem);
    const int tid = threadIdx.x;
    const int wid = tid >> 5, lid = tid & 31;
    const int wm  = wid >> 2, wn = wid & 3;
    const int bm  = blockIdx.y * 128, bn = blockIdx.x * 128;

    constexpr int NST     = TWO ? 2 : 3;
    constexpr uint32_t SSTR = TWO ? 3u * A_BYTES : 2u * A_BYTES;
    constexpr uint32_t BOFF = TWO ? 2u * A_BYTES : 1u * A_BYTES;

    const int llo  = lid & 7;
    const int lr15 = lid & 15;
    const int lhiA = lid >> 4;
    const int lk8B = (lid >> 3) & 1;
    uint32_t aRow[4], bRow[2];
#pragma unroll
    for (int i = 0; i < 4; i++) aRow[i] = (uint32_t)(wm * 64 + i * 16 + lr15) * 128;
#pragma unroll
    for (int p = 0; p < 2; p++)
        bRow[p] = (uint32_t)(wn * 32 + p * 16 + llo + ((lid >> 4) & 1) * 8) * 128;

    float acc[4][4][4];
#pragma unroll
    for (int i = 0; i < 4; i++)
#pragma unroll
        for (int j = 0; j < 4; j++)
#pragma unroll
            for (int q = 0; q < 4; q++) acc[i][j][q] = 0.f;

    auto issue = [&](int kt) {
        const uint32_t st = sb + (uint32_t)(kt % NST) * SSTR;
        const int k0 = kt * BK;
        constexpr int NCH = TWO ? 12 : 8;
#pragma unroll
        for (int u = 0; u < NCH; u++) {
            const int i = tid + u * 256;
            const int arr = i >> 10;
            const int j = i & 1023;
            const int r = j >> 3, c = j & 7;
            const __half* src;
            uint32_t dstOff;
            if (TWO) {
                src = (arr == 0) ? g_XH + (size_t)(bm + r) * D_MODEL + k0 + c * 8
                    : (arr == 1) ? g_XL + (size_t)(bm + r) * D_MODEL + k0 + c * 8
                                 : Bh   + (size_t)(bn + r) * D_MODEL + k0 + c * 8;
                dstOff = (uint32_t)arr * A_BYTES;
            } else {
                src = (arr == 0) ? g_XH + (size_t)(bm + r) * D_MODEL + k0 + c * 8
                                 : Bh   + (size_t)(bn + r) * D_MODEL + k0 + c * 8;
                dstOff = (arr == 0) ? 0u : BOFF;
            }
            const uint32_t dst = st + dstOff +
                                 (uint32_t)r * 128 + (uint32_t)((c ^ (r & 7)) << 4);
            cp_async16(dst, src);
        }
        cp_commit();
    };

    issue(0);
    issue(1);
    if (!TWO) issue(2);

#pragma unroll 1
    for (int t = 0; t < NKT; t++) {
        const int rem = NKT - t;
        if (rem > NST - 1)       cp_wait<NST - 1>();
        else if (rem == 2)       cp_wait<1>();
        else                     cp_wait<0>();
        __syncthreads();

        const uint32_t st = sb + (uint32_t)(t % NST) * SSTR;
#pragma unroll
        for (int s = 0; s < 4; s++) {
            const uint32_t offA = (uint32_t)(((2 * s + lhiA) ^ llo) << 4);
            const uint32_t offB = (uint32_t)(((2 * s + lk8B) ^ llo) << 4);
            uint32_t b[2][4];
#pragma unroll
            for (int p = 0; p < 2; p++)
                ldsm_x4(st + BOFF + bRow[p] + offB, b[p]);

            uint32_t ah[4][4];
#pragma unroll
            for (int i = 0; i < 4; i++) ldsm_x4(st + aRow[i] + offA, ah[i]);
#pragma unroll
            for (int i = 0; i < 4; i++)
#pragma unroll
                for (int j = 0; j < 4; j++)
                    mma16816(acc[i][j], ah[i], b[j >> 1][(j & 1) * 2 + 0],
                                               b[j >> 1][(j & 1) * 2 + 1]);

            if (TWO) {
                uint32_t al[4][4];
#pragma unroll
                for (int i = 0; i < 4; i++)
                    ldsm_x4(st + A_BYTES + aRow[i] + offA, al[i]);
#pragma unroll
                for (int i = 0; i < 4; i++)
#pragma unroll
                    for (int j = 0; j < 4; j++)
                        mma16816(acc[i][j], al[i], b[j >> 1][(j & 1) * 2 + 0],
                                                   b[j >> 1][(j & 1) * 2 + 1]);
            }
        }
        __syncthreads();
        if (t + NST < NKT) issue(t + NST);
    }

    const int g  = lid >> 2;
    const int t2 = (lid & 3) * 2;
#pragma unroll
    for (int i = 0; i < 4; i++) {
        const int row = bm + wm * 64 + i * 16 + g;
#pragma unroll
        for (int j = 0; j < 4; j++) {
            const int col = bn + wn * 32 + j * 8 + t2;
            if (Cf) {
                *(float2*)&Cf[(size_t)row * D_MODEL + col] =
                    make_float2(acc[i][j][0], acc[i][j][1]);
                *(float2*)&Cf[(size_t)(row + 8) * D_MODEL + col] =
                    make_float2(acc[i][j][2], acc[i][j][3]);
            } else {
                *(uint32_t*)&Ch[(size_t)row * D_MODEL + col] =
                    packhi(acc[i][j][0] * scl, acc[i][j][1] * scl);
                *(uint32_t*)&Ch[(size_t)(row + 8) * D_MODEL + col] =
                    packhi(acc[i][j][2] * scl, acc[i][j][3] * scl);
            }
        }
    }
}

// Q pre-scale folds softmax scale AND log2(e) so attention can use exp2:
#define QSCALE 0.18033688011112042f   // 0.125 * 1.4426950408889634

__global__ void __launch_bounds__(256, 2)
gemm_qkv() {
    const int z = blockIdx.z;
    if (z == 0)        // Q: 2-term (Qh = round(accurate Q); one rounding only)
        gemm_core<true >(g_WH, nullptr, g_QH, QSCALE);
    else if (z == 1)
        gemm_core<false>(g_WH + DD, nullptr, g_KH, 1.f);
    else
        gemm_core<false>(g_WH + 2ull * DD, nullptr, g_VH, 1.f);
}
__global__ void __launch_bounds__(256, 2)
gemm_o(float* __restrict__ out) {
    gemm_core<false>(g_WH + 3ull * DD, out, nullptr, 1.f);
}

// ---------------------------------------------------------------------------
// Tensor-core causal flash attention. S = Qh·Kh (single term — Qh carries one
// rounding, below which Ql sat); O += Ph·Vh. exp2 softmax. 3-stage KV pipe.
// ---------------------------------------------------------------------------
#define AST 16640
#define SM_ATTN (3 * AST)    // 49920

__global__ void __launch_bounds__(128, 3)
attn_mma(const int* __restrict__ mask)
{
    extern __shared__ char smem[];
    const uint32_t sb = smem_u32(smem);
    const int tid = threadIdx.x, wid = tid >> 5, lid = tid & 31;
    const int qt = gridDim.x - 1 - blockIdx.x;      // LPT: heavy blocks first
    const int h = blockIdx.y, b = blockIdx.z;
    const int bm = qt * 64;
    const int nt = qt + 1;                // causal: key tiles 0..qt

    // ---- stage Q (hi only) into the stage area, extract fragments ----
    {
#pragma unroll
        for (int u = 0; u < 4; u++) {
            const int i = tid + u * 128;          // 0..511
            const int r = i >> 3, c = i & 7;
            const __half* src = g_QH +
                (size_t)(b * SEQ + bm + r) * D_MODEL + h * HEAD_DIM + c * 8;
            cp_async16(sb + (uint32_t)r * 128 + (uint32_t)((c ^ (r & 7)) << 4), src);
        }
        cp_commit();
        cp_wait<0>();
        __syncthreads();
    }
    uint32_t aQh[4][4];
#pragma unroll
    for (int ks = 0; ks < 4; ks++) {
        const uint32_t off = (uint32_t)(wid * 16 + (lid & 15)) * 128 +
                             (uint32_t)(((2 * ks + (lid >> 4)) ^ (lid & 7)) << 4);
        ldsm_x4(sb + off, aQh[ks]);
    }
    __syncthreads();          // Q extracted; area reused for KV stages

    auto issueKV = [&](int ti) {
        const uint32_t st = sb + (uint32_t)(ti % 3) * AST;
        const int t0 = ti * 64;
#pragma unroll
        for (int u = 0; u < 8; u++) {
            const int i = tid + u * 128;          // 0..1023
            const int arr = i >> 9;               // 0 Kh, 1 Vh
            const int j = i & 511;
            const int r = j >> 3, c = j & 7;
            const __half* base = arr ? g_VH : g_KH;
            const __half* src = base +
                (size_t)(b * SEQ + t0 + r) * D_MODEL + h * HEAD_DIM + c * 8;
            cp_async16(st + (uint32_t)arr * 8192 +
                       (uint32_t)r * 128 + (uint32_t)((c ^ (r & 7)) << 4), src);
        }
        if (tid < 16)
            cp_async16(st + 16384 + tid * 16, mask + b * SEQ + t0 + tid * 4);
        cp_commit();
    };

    issueKV(0);
    if (nt > 1) issueKV(1);
    if (nt > 2) issueKV(2);

    float oreg[8][4];
#pragma unroll
    for (int j = 0; j < 8; j++)
#pragma unroll
        for (int q = 0; q < 4; q++) oreg[j][q] = 0.f;
    float mA = -1e30f, mB = -1e30f, lA = 0.f, lB = 0.f;
    const int q0 = bm + wid * 16 + (lid >> 2);

#pragma unroll 1
    for (int ti = 0; ti < nt; ti++) {
        const int rem = nt - ti;
        if (rem > 2)      cp_wait<2>();
        else if (rem == 2) cp_wait<1>();
        else               cp_wait<0>();
        __syncthreads();
        const uint32_t st = sb + (uint32_t)(ti % 3) * AST;
        const int* msk_s = (const int*)(smem + (ti % 3) * AST + 16384);
        const int t0 = ti * 64;

        // ---- S(log2) = Qh @ Kh^T ----
        float sr[8][4];
#pragma unroll
        for (int j = 0; j < 8; j++)
#pragma unroll
            for (int q = 0; q < 4; q++) sr[j][q] = 0.f;
#pragma unroll
        for (int ks = 0; ks < 4; ks++) {
            uint32_t bh[4][4];
#pragma unroll
            for (int nb = 0; nb < 4; nb++) {
                const uint32_t row = (uint32_t)(nb * 16 + (lid & 7) + ((lid >> 4) & 1) * 8);
                const uint32_t off = row * 128 +
                    (uint32_t)(((2 * ks + ((lid >> 3) & 1)) ^ (lid & 7)) << 4);
                ldsm_x4(st + off, bh[nb]);
            }
#pragma unroll
            for (int j = 0; j < 8; j++)
                mma16816(sr[j], aQh[ks], bh[j >> 1][(j & 1) * 2 + 0],
                                         bh[j >> 1][(j & 1) * 2 + 1]);
        }

        // ---- mask + online softmax (log2 domain) ----
        const bool diag = (ti == qt);
#pragma unroll
        for (int j = 0; j < 8; j++) {
            const int c = j * 8 + (lid & 3) * 2;
            const int kg = t0 + c;
            const int mk0 = msk_s[c], mk1 = msk_s[c + 1];
            if (!mk0) { sr[j][0] = -1e30f; sr[j][2] = -1e30f; }
            if (!mk1) { sr[j][1] = -1e30f; sr[j][3] = -1e30f; }
            if (diag) {
                if (kg     > q0)     sr[j][0] = -1e30f;
                if (kg + 1 > q0)     sr[j][1] = -1e30f;
                if (kg     > q0 + 8) sr[j][2] = -1e30f;
                if (kg + 1 > q0 + 8) sr[j][3] = -1e30f;
            }
        }
        float tmA = -1e30f, tmB = -1e30f;
#pragma unroll
        for (int j = 0; j < 8; j++) {
            tmA = fmaxf(tmA, fmaxf(sr[j][0], sr[j][1]));
            tmB = fmaxf(tmB, fmaxf(sr[j][2], sr[j][3]));
        }
        tmA = fmaxf(tmA, __shfl_xor_sync(0xffffffff, tmA, 1));
        tmA = fmaxf(tmA, __shfl_xor_sync(0xffffffff, tmA, 2));
        tmB = fmaxf(tmB, __shfl_xor_sync(0xffffffff, tmB, 1));
        tmB = fmaxf(tmB, __shfl_xor_sync(0xffffffff, tmB, 2));
        const float nmA = fmaxf(mA, tmA), nmB = fmaxf(mB, tmB);
        const float corrA = ex2f(mA - nmA), corrB = ex2f(mB - nmB);
        mA = nmA; mB = nmB;
        float sA = 0.f, sB = 0.f;
#pragma unroll
        for (int j = 0; j < 8; j++) {
            sr[j][0] = ex2f(sr[j][0] - nmA);
            sr[j][1] = ex2f(sr[j][1] - nmA);
            sr[j][2] = ex2f(sr[j][2] - nmB);
            sr[j][3] = ex2f(sr[j][3] - nmB);
            sA += sr[j][0] + sr[j][1];
            sB += sr[j][2] + sr[j][3];
        }
        sA += __shfl_xor_sync(0xffffffff, sA, 1);
        sA += __shfl_xor_sync(0xffffffff, sA, 2);
        sB += __shfl_xor_sync(0xffffffff, sB, 1);
        sB += __shfl_xor_sync(0xffffffff, sB, 2);
        lA = lA * corrA + sA;
        lB = lB * corrB + sB;
#pragma unroll
        for (int j = 0; j < 8; j++) {
            oreg[j][0] *= corrA; oreg[j][1] *= corrA;
            oreg[j][2] *= corrB; oreg[j][3] *= corrB;
        }

        // ---- O += Ph @ Vh (single term) ----
#pragma unroll
        for (int ks = 0; ks < 4; ks++) {
            uint32_t aph[4];
            aph[0] = packhi(sr[2*ks][0],   sr[2*ks][1]);
            aph[1] = packhi(sr[2*ks][2],   sr[2*ks][3]);
            aph[2] = packhi(sr[2*ks+1][0], sr[2*ks+1][1]);
            aph[3] = packhi(sr[2*ks+1][2], sr[2*ks+1][3]);
            uint32_t vh[4][4];
#pragma unroll
            for (int nb = 0; nb < 4; nb++) {
                const uint32_t row = (uint32_t)(ks * 16 + (lid & 7) + ((lid >> 3) & 1) * 8);
                const uint32_t chk = (uint32_t)(nb * 2 + (lid >> 4));
                const uint32_t off = row * 128 + ((chk ^ (lid & 7)) << 4);
                ldsm_x4t(st + 8192 + off, vh[nb]);
            }
#pragma unroll
            for (int j = 0; j < 8; j++)
                mma16816(oreg[j], aph, vh[j >> 1][(j & 1) * 2 + 0],
                                       vh[j >> 1][(j & 1) * 2 + 1]);
        }

        __syncthreads();
        if (ti + 3 < nt) issueKV(ti + 3);
    }

    // ---- epilogue: normalize, write fp16 hi only (gemm_o is single-term) ----
    const float invA = 1.f / lA, invB = 1.f / lB;
    const size_t rA = (size_t)(b * SEQ + q0) * D_MODEL + h * HEAD_DIM;
    const size_t rB = rA + 8ull * D_MODEL;
#pragma unroll
    for (int j = 0; j < 8; j++) {
        const int col = j * 8 + (lid & 3) * 2;
        *(uint32_t*)&g_XH[rA + col] = packhi(oreg[j][0] * invA, oreg[j][1] * invA);
        *(uint32_t*)&g_XH[rB + col] = packhi(oreg[j][2] * invB, oreg[j][3] * invB);
    }
}

// ---------------------------------------------------------------------------
// Launch. Inputs: x, attention_mask, wq, wk, wv, wo. Output fp32.
// ---------------------------------------------------------------------------
extern "C" void kernel_launch(void* const* d_in, const int* in_sizes, int n_in,
                              void* d_out, int out_size)
{
    const float* x    = (const float*)d_in[0];
    const int*   amsk = (const int*)  d_in[1];
    const float* wq   = (const float*)d_in[2];
    const float* wk   = (const float*)d_in[3];
    const float* wv   = (const float*)d_in[4];
    const float* wo   = (const float*)d_in[5];
    float*       out  = (float*)d_out;

    cudaFuncSetAttribute(gemm_qkv, cudaFuncAttributeMaxDynamicSharedMemorySize, SM_GEMM);
    cudaFuncSetAttribute(gemm_o,   cudaFuncAttributeMaxDynamicSharedMemorySize, SM_GEMM);
    cudaFuncSetAttribute(attn_mma, cudaFuncAttributeMaxDynamicSharedMemorySize, SM_ATTN);

    conv_all<<<dim3(2048, 1, 6), 256>>>(x, wq, wk, wv, wo);

    dim3 gQKV(D_MODEL / 128, M_ROWS / 128, 3);   // (8, 64, 3)
    gemm_qkv<<<gQKV, 256, SM_GEMM>>>();

    dim3 gAttn(SEQ / 64, N_HEADS, BATCH);        // (32, 16, 4)
    attn_mma<<<gAttn, 128, SM_ATTN>>>(amsk);

    dim3 gOut(D_MODEL / 128, M_ROWS / 128, 1);
    gemm_o<<<gOut, 256, SM_GEMM>>>(out);
}